// round 2
// baseline (speedup 1.0000x reference)
#include <cuda_runtime.h>

#define Bn 8
#define Hc 96
#define Wc 128
#define HW (Hc*Wc)
#define CORRC 324

// Scratch (allocation-free rule: __device__ globals)
__device__ float g_cor1[Bn*256*HW];   // conv1x1 output  [B,256,H,W]
__device__ float g_flo1[Bn*128*HW];   // conv7x7 output  [B,128,H,W]
__device__ float g_cat [Bn*256*HW];   // concat(cor2,flo2) [B,256,H,W]

// ---------------------------------------------------------------------------
// 1x1 conv + bias + relu : GEMM [256 x 324] @ [324 x HW] per batch
// block: 128 threads, 256 pixels (2/thread), 32 output channels
// ---------------------------------------------------------------------------
__global__ __launch_bounds__(128) void conv1x1_relu_k(
    const float* __restrict__ in, const float* __restrict__ w,
    const float* __restrict__ bias, float* __restrict__ out)
{
    const int tid = threadIdx.x;
    const int p0 = blockIdx.x * 256 + tid;     // pixel 0 (pixel 1 = p0+128)
    const int coBase = blockIdx.y * 32;
    const int b = blockIdx.z;

    __shared__ float ws[32 * 12];

    float acc0[32], acc1[32];
#pragma unroll
    for (int i = 0; i < 32; i++) { acc0[i] = 0.f; acc1[i] = 0.f; }

    const float* inb = in + (size_t)b * CORRC * HW;

    for (int c0 = 0; c0 < CORRC; c0 += 12) {      // 324 = 27 * 12
        __syncthreads();
#pragma unroll
        for (int i = tid; i < 384; i += 128)
            ws[i] = w[(size_t)(coBase + i / 12) * CORRC + c0 + (i % 12)];
        __syncthreads();

        float x0[12], x1[12];
#pragma unroll
        for (int k = 0; k < 12; k++) {
            const float* pp = inb + (size_t)(c0 + k) * HW;
            x0[k] = pp[p0];
            x1[k] = pp[p0 + 128];
        }
#pragma unroll
        for (int co = 0; co < 32; co++) {
#pragma unroll
            for (int k = 0; k < 12; k++) {
                float wv = ws[co * 12 + k];
                acc0[co] = fmaf(wv, x0[k], acc0[co]);
                acc1[co] = fmaf(wv, x1[k], acc1[co]);
            }
        }
    }

    float* outb = out + (size_t)b * 256 * HW;
#pragma unroll
    for (int co = 0; co < 32; co++) {
        float bv = bias[coBase + co];
        outb[(size_t)(coBase + co) * HW + p0]       = fmaxf(acc0[co] + bv, 0.f);
        outb[(size_t)(coBase + co) * HW + p0 + 128] = fmaxf(acc1[co] + bv, 0.f);
    }
}

// ---------------------------------------------------------------------------
// generic 3x3 conv + bias + relu, pad 1, stride 1
// block: 128 threads (16x8), spatial tile 32x8 (2 px/thread in W), 16 co/block
// out written at channel offset `outChanOff` within a tensor of `outCTotal`
// channels (enables writing the concat buffer / final output directly).
// ---------------------------------------------------------------------------
__global__ __launch_bounds__(128) void conv3x3_relu_k(
    const float* __restrict__ in, int cin,
    const float* __restrict__ w, const float* __restrict__ bias,
    float* __restrict__ out, int coutUsed, int outCTotal, int outChanOff,
    int nCoTiles)
{
    const int tid = threadIdx.x;
    const int tx = tid & 15, ty = tid >> 4;
    const int w0 = blockIdx.x * 32, h0 = blockIdx.y * 8;
    const int coTile = blockIdx.z % nCoTiles;
    const int b = blockIdx.z / nCoTiles;
    const int coBase = coTile * 16;

    __shared__ float st[10][34];
    __shared__ float sw[144];

    float acc[16][2];
#pragma unroll
    for (int i = 0; i < 16; i++) { acc[i][0] = 0.f; acc[i][1] = 0.f; }

    const float* inb = in + (size_t)b * cin * HW;

    for (int ci = 0; ci < cin; ci++) {
        __syncthreads();
        // input tile with 1-px halo: rows h0-1..h0+8, cols w0-1..w0+32
        for (int i = tid; i < 340; i += 128) {
            int r = i / 34, c = i % 34;
            int hh = h0 + r - 1, ww = w0 + c - 1;
            float v = 0.f;
            if ((unsigned)hh < Hc && (unsigned)ww < Wc)
                v = inb[(size_t)ci * HW + hh * Wc + ww];
            st[r][c] = v;
        }
        // 16 co x 9 weights for this ci
        for (int i = tid; i < 144; i += 128) {
            int co = i / 9;
            sw[i] = (coBase + co < coutUsed)
                  ? w[((size_t)(coBase + co) * cin + ci) * 9 + (i % 9)] : 0.f;
        }
        __syncthreads();

        float xv[3][4];
#pragma unroll
        for (int dy = 0; dy < 3; dy++)
#pragma unroll
            for (int dx = 0; dx < 4; dx++)
                xv[dy][dx] = st[ty + dy][2 * tx + dx];

#pragma unroll
        for (int co = 0; co < 16; co++) {
#pragma unroll
            for (int dy = 0; dy < 3; dy++) {
                float a = sw[co * 9 + dy * 3 + 0];
                float bw = sw[co * 9 + dy * 3 + 1];
                float c = sw[co * 9 + dy * 3 + 2];
                acc[co][0] = fmaf(a, xv[dy][0], fmaf(bw, xv[dy][1], fmaf(c, xv[dy][2], acc[co][0])));
                acc[co][1] = fmaf(a, xv[dy][1], fmaf(bw, xv[dy][2], fmaf(c, xv[dy][3], acc[co][1])));
            }
        }
    }

    const int hh = h0 + ty, wwB = w0 + 2 * tx;
    float* outb = out + ((size_t)b * outCTotal + outChanOff) * HW;
#pragma unroll
    for (int co = 0; co < 16; co++) {
        if (coBase + co < coutUsed) {
            float bv = bias[coBase + co];
            float2 v;
            v.x = fmaxf(acc[co][0] + bv, 0.f);
            v.y = fmaxf(acc[co][1] + bv, 0.f);
            *reinterpret_cast<float2*>(&outb[(size_t)(coBase + co) * HW + hh * Wc + wwB]) = v;
        }
    }
}

// ---------------------------------------------------------------------------
// 7x7 conv + bias + relu, pad 3, Cin=2, Cout=128
// block: 256 threads (32x8), 1 px/thread, 16 co/block
// ---------------------------------------------------------------------------
__global__ __launch_bounds__(256) void conv7x7_relu_k(
    const float* __restrict__ in, const float* __restrict__ w,
    const float* __restrict__ bias, float* __restrict__ out)
{
    const int tid = threadIdx.x;
    const int tx = tid & 31, ty = tid >> 5;
    const int w0 = blockIdx.x * 32, h0 = blockIdx.y * 8;
    const int coTile = blockIdx.z & 7;
    const int b = blockIdx.z >> 3;
    const int coBase = coTile * 16;

    __shared__ float st[2][14][38];   // 2 ci, 8+6 rows, 32+6 cols
    __shared__ float sw[16 * 2 * 49]; // 1568 weights for this co tile

    const float* inb = in + (size_t)b * 2 * HW;
    for (int i = tid; i < 2 * 14 * 38; i += 256) {
        int ci = i / 532, r = (i % 532) / 38, c = i % 38;
        int hh = h0 + r - 3, ww = w0 + c - 3;
        float v = 0.f;
        if ((unsigned)hh < Hc && (unsigned)ww < Wc)
            v = inb[(size_t)ci * HW + hh * Wc + ww];
        st[ci][r][c] = v;
    }
    for (int i = tid; i < 1568; i += 256)
        sw[i] = w[(size_t)coBase * 98 + i];   // [co][ci][7][7], 98 floats/co
    __syncthreads();

    float acc[16];
#pragma unroll
    for (int i = 0; i < 16; i++) acc[i] = 0.f;

#pragma unroll
    for (int ci = 0; ci < 2; ci++) {
#pragma unroll
        for (int dy = 0; dy < 7; dy++) {
            float xv[7];
#pragma unroll
            for (int k = 0; k < 7; k++) xv[k] = st[ci][ty + dy][tx + k];
#pragma unroll
            for (int co = 0; co < 16; co++) {
#pragma unroll
                for (int dx = 0; dx < 7; dx++)
                    acc[co] = fmaf(sw[co * 98 + ci * 49 + dy * 7 + dx], xv[dx], acc[co]);
            }
        }
    }

    const int hh = h0 + ty, ww = w0 + tx;
    float* outb = out + (size_t)b * 128 * HW;
#pragma unroll
    for (int co = 0; co < 16; co++)
        outb[(size_t)(coBase + co) * HW + hh * Wc + ww] =
            fmaxf(acc[co] + bias[coBase + co], 0.f);
}

// append flow into output channels 126..127
__global__ void concat_flow_k(const float* __restrict__ flow, float* __restrict__ out)
{
    int i = blockIdx.x * 256 + threadIdx.x;
    if (i < Bn * 2 * HW) {
        int b = i / (2 * HW);
        int r = i % (2 * HW);
        out[(size_t)b * 128 * HW + (size_t)126 * HW + r] = flow[i];
    }
}

extern "C" void kernel_launch(void* const* d_in, const int* in_sizes, int n_in,
                              void* d_out, int out_size)
{
    const float* flow = (const float*)d_in[0];
    const float* corr = (const float*)d_in[1];
    const float* wc1  = (const float*)d_in[2];
    const float* bc1  = (const float*)d_in[3];
    const float* wc2  = (const float*)d_in[4];
    const float* bc2  = (const float*)d_in[5];
    const float* wf1  = (const float*)d_in[6];
    const float* bf1  = (const float*)d_in[7];
    const float* wf2  = (const float*)d_in[8];
    const float* bf2  = (const float*)d_in[9];
    const float* wo   = (const float*)d_in[10];
    const float* bo   = (const float*)d_in[11];
    float* out = (float*)d_out;

    float *cor1, *flo1, *cat;
    cudaGetSymbolAddress((void**)&cor1, g_cor1);
    cudaGetSymbolAddress((void**)&flo1, g_flo1);
    cudaGetSymbolAddress((void**)&cat,  g_cat);

    // cor = relu(conv1x1(corr))           [B,256,H,W]
    conv1x1_relu_k<<<dim3(HW / 256, 256 / 32, Bn), 128>>>(corr, wc1, bc1, cor1);
    // flo = relu(conv7x7(flow))           [B,128,H,W]
    conv7x7_relu_k<<<dim3(Wc / 32, Hc / 8, Bn * 8), 256>>>(flow, wf1, bf1, flo1);
    // cor = relu(conv3x3(cor)) -> cat[:,0:192]
    conv3x3_relu_k<<<dim3(Wc / 32, Hc / 8, Bn * 12), 128>>>(cor1, 256, wc2, bc2, cat, 192, 256, 0, 12);
    // flo = relu(conv3x3(flo)) -> cat[:,192:256]
    conv3x3_relu_k<<<dim3(Wc / 32, Hc / 8, Bn * 4), 128>>>(flo1, 128, wf2, bf2, cat, 64, 256, 192, 4);
    // out = relu(conv3x3(cat)) -> d_out[:,0:126]
    conv3x3_relu_k<<<dim3(Wc / 32, Hc / 8, Bn * 8), 128>>>(cat, 256, wo, bo, out, 126, 128, 0, 8);
    // d_out[:,126:128] = flow
    concat_flow_k<<<(Bn * 2 * HW + 255) / 256, 256>>>(flow, out);
}

// round 4
// speedup vs baseline: 2.3228x; 2.3228x over previous
#include <cuda_runtime.h>
#include <cuda_fp16.h>
#include <stdint.h>

#define Bn 8
#define Hc 96
#define Wc 128
#define HW (Hc*Wc)

// ---------------- scratch (__device__ globals; allocation-free rule) -------
__device__ __half g_corr_h[(size_t)Bn*HW*384];
__device__ __half g_corr_l[(size_t)Bn*HW*384];
__device__ __half g_cor1_h[(size_t)Bn*HW*256];
__device__ __half g_cor1_l[(size_t)Bn*HW*256];
__device__ __half g_flo1_h[(size_t)Bn*HW*128];
__device__ __half g_flo1_l[(size_t)Bn*HW*128];
__device__ __half g_cat_h[(size_t)Bn*HW*256];
__device__ __half g_cat_l[(size_t)Bn*HW*256];
__device__ __half g_wc1_h[1*256*384], g_wc1_l[1*256*384];
__device__ __half g_wc2_h[9*256*256], g_wc2_l[9*256*256];
__device__ __half g_wf2_h[9*128*128], g_wf2_l[9*128*128];
__device__ __half g_wo_h [9*128*256], g_wo_l [9*128*256];

// ---------------- helpers ---------------------------------------------------
__device__ __forceinline__ uint32_t s2u(const void* p) {
    uint32_t a;
    asm("{ .reg .u64 t; cvta.to.shared.u64 t, %1; cvt.u32.u64 %0, t; }"
        : "=r"(a) : "l"(p));
    return a;
}
// xor swizzle for 128B rows: flips bits[4:6] with (row&7)
#define SWZ(x) ((x) ^ (((x) >> 3) & 0x70))

__device__ __forceinline__ void ldsm4(uint32_t* r, uint32_t addr) {
    asm volatile("ldmatrix.sync.aligned.m8n8.x4.shared.b16 {%0,%1,%2,%3}, [%4];"
        : "=r"(r[0]), "=r"(r[1]), "=r"(r[2]), "=r"(r[3]) : "r"(addr));
}
__device__ __forceinline__ void mma16816(float* d, const uint32_t* a,
                                          uint32_t b0, uint32_t b1) {
    asm volatile(
        "mma.sync.aligned.m16n8k16.row.col.f32.f16.f16.f32 "
        "{%0,%1,%2,%3}, {%4,%5,%6,%7}, {%8,%9}, {%0,%1,%2,%3};"
        : "+f"(d[0]), "+f"(d[1]), "+f"(d[2]), "+f"(d[3])
        : "r"(a[0]), "r"(a[1]), "r"(a[2]), "r"(a[3]), "r"(b0), "r"(b1));
}

// ---------------- weight prep: OIHW fp32 -> [tap][coPad][Cpad] fp16 hi/lo ---
__global__ void wprep_k(const float* __restrict__ w, int cout, int cin, int taps,
                        int coPad, int Cpad,
                        __half* __restrict__ wh, __half* __restrict__ wl)
{
    size_t total = (size_t)taps * coPad * Cpad;
    for (size_t i = (size_t)blockIdx.x * blockDim.x + threadIdx.x; i < total;
         i += (size_t)gridDim.x * blockDim.x) {
        int ci = (int)(i % Cpad);
        size_t t = i / Cpad;
        int co = (int)(t % coPad);
        int tap = (int)(t / coPad);
        float v = 0.f;
        if (co < cout && ci < cin)
            v = w[((size_t)co * cin + ci) * taps + tap];
        __half h = __float2half(v);
        wh[i] = h;
        wl[i] = __float2half(v - __half2float(h));
    }
}

// ---------------- corr NCHW fp32 -> NHWC fp16 hi/lo (Cpad=384, zero pad) ----
__global__ __launch_bounds__(256) void corr2nhwc_k(
    const float* __restrict__ corr,
    __half* __restrict__ oh, __half* __restrict__ ol)
{
    const int c0 = blockIdx.x * 32, h = blockIdx.y, b = blockIdx.z;
    __shared__ float t[32][129];
    for (int i = threadIdx.x; i < 32 * 128; i += 256) {
        int ci = i >> 7, px = i & 127;
        float v = 0.f;
        if (c0 + ci < 324)
            v = corr[((size_t)b * 324 + c0 + ci) * HW + h * Wc + px];
        t[ci][px] = v;
    }
    __syncthreads();
    for (int i = threadIdx.x; i < 32 * 128; i += 256) {
        int px = i >> 5, ci = i & 31;
        float v = t[ci][px];
        __half hh = __float2half(v);
        size_t o = (((size_t)b * Hc + h) * Wc + px) * 384 + c0 + ci;
        oh[o] = hh;
        ol[o] = __float2half(v - __half2float(hh));
    }
}

// ---------------- conv7x7 (Cin=2, Cout=128) fp32 -> NHWC fp16 hi/lo ---------
__global__ __launch_bounds__(256) void conv7x7_relu_k(
    const float* __restrict__ in, const float* __restrict__ w,
    const float* __restrict__ bias,
    __half* __restrict__ oh, __half* __restrict__ ol)
{
    const int tid = threadIdx.x;
    const int tx = tid & 31, ty = tid >> 5;
    const int w0 = blockIdx.x * 32, h0 = blockIdx.y * 8;
    const int coTile = blockIdx.z & 7;
    const int b = blockIdx.z >> 3;
    const int coBase = coTile * 16;

    __shared__ float st[2][14][38];
    __shared__ float sw[16 * 2 * 49];

    const float* inb = in + (size_t)b * 2 * HW;
    for (int i = tid; i < 2 * 14 * 38; i += 256) {
        int ci = i / 532, r = (i % 532) / 38, c = i % 38;
        int hh = h0 + r - 3, ww = w0 + c - 3;
        float v = 0.f;
        if ((unsigned)hh < Hc && (unsigned)ww < Wc)
            v = inb[(size_t)ci * HW + hh * Wc + ww];
        st[ci][r][c] = v;
    }
    for (int i = tid; i < 1568; i += 256)
        sw[i] = w[(size_t)coBase * 98 + i];
    __syncthreads();

    float acc[16];
#pragma unroll
    for (int i = 0; i < 16; i++) acc[i] = 0.f;

#pragma unroll
    for (int ci = 0; ci < 2; ci++)
#pragma unroll
        for (int dy = 0; dy < 7; dy++) {
            float xv[7];
#pragma unroll
            for (int k = 0; k < 7; k++) xv[k] = st[ci][ty + dy][tx + k];
#pragma unroll
            for (int co = 0; co < 16; co++)
#pragma unroll
                for (int dx = 0; dx < 7; dx++)
                    acc[co] = fmaf(sw[co * 98 + ci * 49 + dy * 7 + dx], xv[dx], acc[co]);
        }

    const int hh = h0 + ty, ww = w0 + tx;
    __align__(16) __half vh[16], vl[16];
#pragma unroll
    for (int co = 0; co < 16; co++) {
        float v = fmaxf(acc[co] + bias[coBase + co], 0.f);
        vh[co] = __float2half(v);
        vl[co] = __float2half(v - __half2float(vh[co]));
    }
    size_t base = (((size_t)b * Hc + hh) * Wc + ww) * 128 + coBase;
    reinterpret_cast<uint4*>(oh + base)[0] = reinterpret_cast<uint4*>(vh)[0];
    reinterpret_cast<uint4*>(oh + base)[1] = reinterpret_cast<uint4*>(vh)[1];
    reinterpret_cast<uint4*>(ol + base)[0] = reinterpret_cast<uint4*>(vl)[0];
    reinterpret_cast<uint4*>(ol + base)[1] = reinterpret_cast<uint4*>(vl)[1];
}

// ---------------- HMMA conv-as-GEMM -----------------------------------------
// Block: 256 thr, 8 warps. Output tile: 128co x 128px (one image row).
// Warp w: co [ (w>>1)*32, +32 ), px [ (w&1)*64, +64 ): 16 mma tiles (m16n8).
// K loop: ci chunks of 64; per chunk B (3 dy rows x hi/lo, halo'd) resident,
// A (per tap, wh/wl) double buffered. 3 precision passes fused:
//   A=wh: B in {xh, xl};  A=wl: B in {xh}.
// smem: A 2x16KB @0 ; B 6x16640B @32768 (reused by epilogue transpose).
#define SMEM_BYTES 132608

__global__ __launch_bounds__(256) void conv_mma_k(
    const __half* __restrict__ ah, const __half* __restrict__ al,
    int Cpad, int kcNum,
    const __half* __restrict__ wgh, const __half* __restrict__ wgl,
    int coPad, const float* __restrict__ bias, int coutUsed,
    int taps, int kw, int kr,
    __half* __restrict__ oh, __half* __restrict__ ol, int outCpad, int outCoff,
    float* __restrict__ of32)
{
    extern __shared__ __align__(16) char smem[];
    const uint32_t sA = s2u(smem);
    const uint32_t sB = sA + 32768u;

    const int tid = threadIdx.x;
    const int warp = tid >> 5, lane = tid & 31;
    const int mt = blockIdx.x, h = blockIdx.y, b = blockIdx.z;
    const int cbw = (warp >> 1) * 32;
    const int nbw = (warp & 1) * 64;
    const int gid = lane >> 2, tig = lane & 3;
    const int midx = lane >> 3, l7 = lane & 7;

    float d[16][4];
#pragma unroll
    for (int i = 0; i < 16; i++)
#pragma unroll
        for (int j = 0; j < 4; j++) d[i][j] = 0.f;

    const int nT = (2 * kr + 1) * 2;    // B tiles: dy rows x (hi,lo)
    const int nAt = taps * 2;           // A tiles: tap x (wh,wl)

    for (int kc = 0; kc < kcNum; kc++) {
        __syncthreads();
        // ---- stage B tiles: [130 px-rows][64 ci] fp16, swizzled
        const int totB = nT * 1040;     // 130*8 uint4 per tile
        for (int i = tid; i < totB; i += 256) {
            int tIdx = i / 1040, rem = i - tIdx * 1040;
            int row = rem >> 3, c16 = rem & 7;
            int px = row - 1;
            int hh = h + (tIdx >> 1) - kr;
            const __half* src = (tIdx & 1) ? al : ah;
            uint4 v = make_uint4(0u, 0u, 0u, 0u);
            if ((unsigned)px < Wc && (unsigned)hh < Hc)
                v = *reinterpret_cast<const uint4*>(
                    src + (((size_t)b * Hc + hh) * Wc + px) * Cpad + kc * 64 + c16 * 8);
            *reinterpret_cast<uint4*>(smem + 32768 + tIdx * 16640 +
                                      SWZ(row * 128 + c16 * 16)) = v;
        }
        // ---- stage A tile 0 (tap 0, wh)
#pragma unroll
        for (int j = 0; j < 4; j++) {
            int i = tid + j * 256;
            int row = i >> 3, c16 = i & 7;
            uint4 v = *reinterpret_cast<const uint4*>(
                wgh + ((size_t)0 * coPad + mt * 128 + row) * Cpad + kc * 64 + c16 * 8);
            *reinterpret_cast<uint4*>(smem + SWZ(row * 128 + c16 * 16)) = v;
        }
        __syncthreads();

        for (int t = 0; t < nAt; t++) {
            // prefetch next A tile into regs
            uint4 rg[4];
            const int tn = t + 1;
            if (tn < nAt) {
                int tap = tn >> 1;
                const __half* ws = (tn & 1) ? wgl : wgh;
#pragma unroll
                for (int j = 0; j < 4; j++) {
                    int i = tid + j * 256;
                    int row = i >> 3, c16 = i & 7;
                    rg[j] = *reinterpret_cast<const uint4*>(
                        ws + ((size_t)tap * coPad + mt * 128 + row) * Cpad + kc * 64 + c16 * 8);
                }
            }
            // compute with A buffer t&1
            const int tap = t >> 1, asel = t & 1;
            const int dyI = tap / kw, dx = tap % kw - kr;
            const uint32_t Ab = sA + (uint32_t)(t & 1) * 16384u;
            const int nB = asel ? 1 : 2;
#pragma unroll
            for (int ks = 0; ks < 4; ks++) {
                uint32_t a[2][4];
#pragma unroll
                for (int mi = 0; mi < 2; mi++) {
                    uint32_t ad = Ab + SWZ((uint32_t)((cbw + mi * 16 + ((midx & 1) << 3) + l7) * 128
                                                      + (2 * ks + (midx >> 1)) * 16));
                    ldsm4(a[mi], ad);
                }
                for (int bs = 0; bs < nB; bs++) {
                    const int bsel = asel ? 0 : bs;   // wl pairs with xh only
                    const uint32_t Bt = sB + (uint32_t)((dyI * 2 + bsel) * 16640);
                    uint32_t bf[4][4];
#pragma unroll
                    for (int np = 0; np < 4; np++) {
                        int brow = nbw + np * 16 + ((midx >> 1) << 3) + l7 + 1 + dx;
                        uint32_t bd = Bt + SWZ((uint32_t)(brow * 128 + (2 * ks + (midx & 1)) * 16));
                        ldsm4(bf[np], bd);
                    }
#pragma unroll
                    for (int mi = 0; mi < 2; mi++)
#pragma unroll
                        for (int ni = 0; ni < 8; ni++)
                            mma16816(d[mi * 8 + ni], a[mi],
                                     bf[ni >> 1][(ni & 1) * 2], bf[ni >> 1][(ni & 1) * 2 + 1]);
                }
            }
            // store prefetched A
            if (tn < nAt) {
#pragma unroll
                for (int j = 0; j < 4; j++) {
                    int i = tid + j * 256;
                    int row = i >> 3, c16 = i & 7;
                    *reinterpret_cast<uint4*>(smem + (tn & 1) * 16384 +
                                              SWZ(row * 128 + c16 * 16)) = rg[j];
                }
            }
            __syncthreads();
        }
    }

    // ---- epilogue: bias+relu, transpose through smem (B region reused)
    float bias4[4];
#pragma unroll
    for (int k2 = 0; k2 < 4; k2++) {
        int gco = mt * 128 + cbw + (k2 >> 1) * 16 + gid + (k2 & 1) * 8;
        bias4[k2] = (gco < coutUsed) ? bias[gco] : 0.f;
    }
    __syncthreads();

    if (of32) {
        // FO: [co 128][px 128 + pad4] fp32 at smem+32768
#pragma unroll
        for (int mi = 0; mi < 2; mi++)
#pragma unroll
            for (int ni = 0; ni < 8; ni++)
#pragma unroll
                for (int k = 0; k < 4; k++) {
                    int co = cbw + mi * 16 + gid + ((k >> 1) << 3);
                    int px = nbw + ni * 8 + 2 * tig + (k & 1);
                    float v = fmaxf(d[mi * 8 + ni][k] + bias4[mi * 2 + (k >> 1)], 0.f);
                    *reinterpret_cast<float*>(smem + 32768 + (co * 132 + px) * 4) = v;
                }
        __syncthreads();
        for (int i = tid; i < 128 * 32; i += 256) {
            int row = i >> 5, q = i & 31;
            if (mt * 128 + row < coutUsed) {
                uint4 v = *reinterpret_cast<uint4*>(smem + 32768 + (row * 132 + q * 4) * 4);
                *reinterpret_cast<uint4*>(
                    of32 + (((size_t)b * 128 + mt * 128 + row) * Hc + h) * Wc + q * 4) = v;
            }
        }
    } else {
        // HO/LO: [px 128][co 128 + pad8] fp16 at smem+32768 / +34816
#pragma unroll
        for (int mi = 0; mi < 2; mi++)
#pragma unroll
            for (int ni = 0; ni < 8; ni++)
#pragma unroll
                for (int k = 0; k < 4; k++) {
                    int co = cbw + mi * 16 + gid + ((k >> 1) << 3);
                    int px = nbw + ni * 8 + 2 * tig + (k & 1);
                    float v = fmaxf(d[mi * 8 + ni][k] + bias4[mi * 2 + (k >> 1)], 0.f);
                    __half hv = __float2half(v);
                    __half lv = __float2half(v - __half2float(hv));
                    *reinterpret_cast<__half*>(smem + 32768 + px * 272 + co * 2) = hv;
                    *reinterpret_cast<__half*>(smem + 32768 + 34816 + px * 272 + co * 2) = lv;
                }
        __syncthreads();
        for (int i = tid; i < 128 * 16; i += 256) {
            int row = i >> 4, q = i & 15;     // row = px, q = co/8 group
            int gcoB = mt * 128 + q * 8;
            size_t dst = (((size_t)b * Hc + h) * Wc + row) * outCpad + outCoff + mt * 128 + q * 8;
            uint4 vh = *reinterpret_cast<uint4*>(smem + 32768 + row * 272 + q * 16);
            uint4 vl = *reinterpret_cast<uint4*>(smem + 32768 + 34816 + row * 272 + q * 16);
            if (gcoB + 8 <= coutUsed) {
                *reinterpret_cast<uint4*>(oh + dst) = vh;
                *reinterpret_cast<uint4*>(ol + dst) = vl;
            } else if (gcoB < coutUsed) {
                const __half* ph = reinterpret_cast<const __half*>(&vh);
                const __half* pl = reinterpret_cast<const __half*>(&vl);
                for (int e = 0; e < coutUsed - gcoB; e++) {
                    oh[dst + e] = ph[e];
                    ol[dst + e] = pl[e];
                }
            }
        }
    }
}

// append flow into output channels 126..127 (NCHW fp32)
__global__ void concat_flow_k(const float* __restrict__ flow, float* __restrict__ out)
{
    int i = blockIdx.x * 256 + threadIdx.x;
    if (i < Bn * 2 * HW) {
        int b = i / (2 * HW);
        int r = i % (2 * HW);
        out[(size_t)b * 128 * HW + (size_t)126 * HW + r] = flow[i];
    }
}

// ---------------------------------------------------------------------------
extern "C" void kernel_launch(void* const* d_in, const int* in_sizes, int n_in,
                              void* d_out, int out_size)
{
    const float* flow = (const float*)d_in[0];
    const float* corr = (const float*)d_in[1];
    const float* wc1  = (const float*)d_in[2];
    const float* bc1  = (const float*)d_in[3];
    const float* wc2  = (const float*)d_in[4];
    const float* bc2  = (const float*)d_in[5];
    const float* wf1  = (const float*)d_in[6];
    const float* bf1  = (const float*)d_in[7];
    const float* wf2  = (const float*)d_in[8];
    const float* bf2  = (const float*)d_in[9];
    const float* wo   = (const float*)d_in[10];
    const float* bo   = (const float*)d_in[11];
    float* out = (float*)d_out;

    __half *corrh, *corrl, *cor1h, *cor1l, *flo1h, *flo1l, *cath, *catl;
    __half *wc1h, *wc1l, *wc2h, *wc2l, *wf2h, *wf2l, *woh, *wol;
    cudaGetSymbolAddress((void**)&corrh, g_corr_h); cudaGetSymbolAddress((void**)&corrl, g_corr_l);
    cudaGetSymbolAddress((void**)&cor1h, g_cor1_h); cudaGetSymbolAddress((void**)&cor1l, g_cor1_l);
    cudaGetSymbolAddress((void**)&flo1h, g_flo1_h); cudaGetSymbolAddress((void**)&flo1l, g_flo1_l);
    cudaGetSymbolAddress((void**)&cath,  g_cat_h);  cudaGetSymbolAddress((void**)&catl,  g_cat_l);
    cudaGetSymbolAddress((void**)&wc1h,  g_wc1_h);  cudaGetSymbolAddress((void**)&wc1l,  g_wc1_l);
    cudaGetSymbolAddress((void**)&wc2h,  g_wc2_h);  cudaGetSymbolAddress((void**)&wc2l,  g_wc2_l);
    cudaGetSymbolAddress((void**)&wf2h,  g_wf2_h);  cudaGetSymbolAddress((void**)&wf2l,  g_wf2_l);
    cudaGetSymbolAddress((void**)&woh,   g_wo_h);   cudaGetSymbolAddress((void**)&wol,   g_wo_l);

    cudaFuncSetAttribute(conv_mma_k, cudaFuncAttributeMaxDynamicSharedMemorySize, SMEM_BYTES);

    // prep
    wprep_k<<<128, 256>>>(wc1, 256, 324, 1, 256, 384, wc1h, wc1l);
    wprep_k<<<256, 256>>>(wc2, 192, 256, 9, 256, 256, wc2h, wc2l);
    wprep_k<<<128, 256>>>(wf2,  64, 128, 9, 128, 128, wf2h, wf2l);
    wprep_k<<<128, 256>>>(wo,  126, 256, 9, 128, 256, woh, wol);
    corr2nhwc_k<<<dim3(12, Hc, Bn), 256>>>(corr, corrh, corrl);

    // flo1 = relu(conv7x7(flow)) -> NHWC fp16 hi/lo (Cpad 128)
    conv7x7_relu_k<<<dim3(Wc / 32, Hc / 8, Bn * 8), 256>>>(flow, wf1, bf1, flo1h, flo1l);

    // cor1 = relu(conv1x1(corr))   [256ch, Cin 324->384]
    conv_mma_k<<<dim3(2, Hc, Bn), 256, SMEM_BYTES>>>(
        corrh, corrl, 384, 6, wc1h, wc1l, 256, bc1, 256, 1, 1, 0,
        cor1h, cor1l, 256, 0, nullptr);
    // cat[:,0:192] = relu(conv3x3(cor1))
    conv_mma_k<<<dim3(2, Hc, Bn), 256, SMEM_BYTES>>>(
        cor1h, cor1l, 256, 4, wc2h, wc2l, 256, bc2, 192, 9, 3, 1,
        cath, catl, 256, 0, nullptr);
    // cat[:,192:256] = relu(conv3x3(flo1))
    conv_mma_k<<<dim3(1, Hc, Bn), 256, SMEM_BYTES>>>(
        flo1h, flo1l, 128, 2, wf2h, wf2l, 128, bf2, 64, 9, 3, 1,
        cath, catl, 256, 192, nullptr);
    // d_out[:,0:126] = relu(conv3x3(cat))  (fp32 NCHW)
    conv_mma_k<<<dim3(1, Hc, Bn), 256, SMEM_BYTES>>>(
        cath, catl, 256, 4, woh, wol, 128, bo, 126, 9, 3, 1,
        nullptr, nullptr, 0, 0, out);
    // d_out[:,126:128] = flow
    concat_flow_k<<<(Bn * 2 * HW + 255) / 256, 256>>>(flow, out);
}

// round 5
// speedup vs baseline: 4.0631x; 1.7492x over previous
#include <cuda_runtime.h>
#include <cuda_fp16.h>
#include <stdint.h>

#define Bn 8
#define Hc 96
#define Wc 128
#define HW (Hc*Wc)

// ---------------- scratch (__device__ globals; allocation-free rule) -------
__device__ __half g_corr_h[(size_t)Bn*HW*384];
__device__ __half g_cor1_h[(size_t)Bn*HW*256];
__device__ __half g_flo1_h[(size_t)Bn*HW*128];
__device__ __half g_cat_h [(size_t)Bn*HW*256];
__device__ __half g_wc1_h[1*256*384], g_wc1_l[1*256*384];
__device__ __half g_wc2_h[9*256*256], g_wc2_l[9*256*256];
__device__ __half g_wf2_h[9*128*128], g_wf2_l[9*128*128];
__device__ __half g_wo_h [9*128*256], g_wo_l [9*128*256];

// ---------------- helpers ---------------------------------------------------
__device__ __forceinline__ uint32_t s2u(const void* p) {
    uint32_t a;
    asm("{ .reg .u64 t; cvta.to.shared.u64 t, %1; cvt.u32.u64 %0, t; }"
        : "=r"(a) : "l"(p));
    return a;
}
#define SWZ(x) ((x) ^ (((x) >> 3) & 0x70))

__device__ __forceinline__ void ldsm4(uint32_t* r, uint32_t addr) {
    asm volatile("ldmatrix.sync.aligned.m8n8.x4.shared.b16 {%0,%1,%2,%3}, [%4];"
        : "=r"(r[0]), "=r"(r[1]), "=r"(r[2]), "=r"(r[3]) : "r"(addr));
}
__device__ __forceinline__ void mma16816(float* d, const uint32_t* a,
                                          uint32_t b0, uint32_t b1) {
    asm volatile(
        "mma.sync.aligned.m16n8k16.row.col.f32.f16.f16.f32 "
        "{%0,%1,%2,%3}, {%4,%5,%6,%7}, {%8,%9}, {%0,%1,%2,%3};"
        : "+f"(d[0]), "+f"(d[1]), "+f"(d[2]), "+f"(d[3])
        : "r"(a[0]), "r"(a[1]), "r"(a[2]), "r"(a[3]), "r"(b0), "r"(b1));
}
// cp.async 16B with zero-fill when pred==false (no src read at size 0)
__device__ __forceinline__ void cpa16(uint32_t s, const void* g, bool p) {
    asm volatile("cp.async.ca.shared.global [%0], [%1], 16, %2;"
        :: "r"(s), "l"(g), "r"(p ? 16u : 0u));
}
__device__ __forceinline__ void cpa_commit() {
    asm volatile("cp.async.commit_group;" ::: "memory");
}
__device__ __forceinline__ void cpa_wait0() {
    asm volatile("cp.async.wait_group 0;" ::: "memory");
}

// ---------------- weight prep: OIHW fp32 -> [tap][coPad][Cpad] fp16 hi/lo ---
__global__ void wprep_k(const float* __restrict__ w, int cout, int cin, int taps,
                        int coPad, int Cpad,
                        __half* __restrict__ wh, __half* __restrict__ wl)
{
    size_t total = (size_t)taps * coPad * Cpad;
    for (size_t i = (size_t)blockIdx.x * blockDim.x + threadIdx.x; i < total;
         i += (size_t)gridDim.x * blockDim.x) {
        int ci = (int)(i % Cpad);
        size_t t = i / Cpad;
        int co = (int)(t % coPad);
        int tap = (int)(t / coPad);
        float v = 0.f;
        if (co < cout && ci < cin)
            v = w[((size_t)co * cin + ci) * taps + tap];
        __half h = __float2half(v);
        wh[i] = h;
        wl[i] = __float2half(v - __half2float(h));
    }
}

// ---------------- corr NCHW fp32 -> NHWC fp16 (Cpad=384, zero pad) ----------
__global__ __launch_bounds__(256) void corr2nhwc_k(
    const float* __restrict__ corr, __half* __restrict__ oh)
{
    const int c0 = blockIdx.x * 32, h = blockIdx.y, b = blockIdx.z;
    __shared__ float t[32][129];
    for (int i = threadIdx.x; i < 32 * 128; i += 256) {
        int ci = i >> 7, px = i & 127;
        float v = 0.f;
        if (c0 + ci < 324)
            v = corr[((size_t)b * 324 + c0 + ci) * HW + h * Wc + px];
        t[ci][px] = v;
    }
    __syncthreads();
    for (int i = threadIdx.x; i < 32 * 128; i += 256) {
        int px = i >> 5, ci = i & 31;
        size_t o = (((size_t)b * Hc + h) * Wc + px) * 384 + c0 + ci;
        oh[o] = __float2half(t[ci][px]);
    }
}

// ---------------- conv7x7 (Cin=2, Cout=128) fp32 -> NHWC fp16 ---------------
__global__ __launch_bounds__(256) void conv7x7_relu_k(
    const float* __restrict__ in, const float* __restrict__ w,
    const float* __restrict__ bias, __half* __restrict__ oh)
{
    const int tid = threadIdx.x;
    const int tx = tid & 31, ty = tid >> 5;
    const int w0 = blockIdx.x * 32, h0 = blockIdx.y * 8;
    const int coTile = blockIdx.z & 7;
    const int b = blockIdx.z >> 3;
    const int coBase = coTile * 16;

    __shared__ float st[2][14][38];
    __shared__ float sw[16 * 2 * 49];

    const float* inb = in + (size_t)b * 2 * HW;
    for (int i = tid; i < 2 * 14 * 38; i += 256) {
        int ci = i / 532, r = (i % 532) / 38, c = i % 38;
        int hh = h0 + r - 3, ww = w0 + c - 3;
        float v = 0.f;
        if ((unsigned)hh < Hc && (unsigned)ww < Wc)
            v = inb[(size_t)ci * HW + hh * Wc + ww];
        st[ci][r][c] = v;
    }
    for (int i = tid; i < 1568; i += 256)
        sw[i] = w[(size_t)coBase * 98 + i];
    __syncthreads();

    float acc[16];
#pragma unroll
    for (int i = 0; i < 16; i++) acc[i] = 0.f;

#pragma unroll
    for (int ci = 0; ci < 2; ci++)
#pragma unroll
        for (int dy = 0; dy < 7; dy++) {
            float xv[7];
#pragma unroll
            for (int k = 0; k < 7; k++) xv[k] = st[ci][ty + dy][tx + k];
#pragma unroll
            for (int co = 0; co < 16; co++)
#pragma unroll
                for (int dx = 0; dx < 7; dx++)
                    acc[co] = fmaf(sw[co * 98 + ci * 49 + dy * 7 + dx], xv[dx], acc[co]);
        }

    const int hh = h0 + ty, ww = w0 + tx;
    __align__(16) __half vh[16];
#pragma unroll
    for (int co = 0; co < 16; co++)
        vh[co] = __float2half(fmaxf(acc[co] + bias[coBase + co], 0.f));
    size_t base = (((size_t)b * Hc + hh) * Wc + ww) * 128 + coBase;
    reinterpret_cast<uint4*>(oh + base)[0] = reinterpret_cast<uint4*>(vh)[0];
    reinterpret_cast<uint4*>(oh + base)[1] = reinterpret_cast<uint4*>(vh)[1];
}

// ---------------- HMMA conv-as-GEMM (2-pass weight split) -------------------
// Block: 256 thr / 8 warps; out tile 128co x 128px (one image row).
// K loop: kc chunks of 64 ci; B (dy rows of xh, halo'd) staged once per kc and
// reused by all taps x {wh,wl}; A double-buffered via cp.async.
// smem: A 2x16KB @0 ; B (2kr+1)x16640 @32768 (region reused by epilogue).
#define SMEM_BYTES 100352

__global__ __launch_bounds__(256, 2) void conv_mma_k(
    const __half* __restrict__ ah, int Cpad, int kcNum,
    const __half* __restrict__ wgh, const __half* __restrict__ wgl,
    int coPad, const float* __restrict__ bias, int coutUsed,
    int taps, int kw, int kr,
    __half* __restrict__ oh, int outCpad, int outCoff,
    float* __restrict__ of32)
{
    extern __shared__ __align__(16) char smem[];
    const uint32_t sA = s2u(smem);
    const uint32_t sB = sA + 32768u;

    const int tid = threadIdx.x;
    const int warp = tid >> 5, lane = tid & 31;
    const int mt = blockIdx.x, h = blockIdx.y, b = blockIdx.z;
    const int cbw = (warp >> 1) * 32;
    const int nbw = (warp & 1) * 64;
    const int gid = lane >> 2, tig = lane & 3;
    const int midx = lane >> 3, l7 = lane & 7;

    float d[16][4];
#pragma unroll
    for (int i = 0; i < 16; i++)
#pragma unroll
        for (int j = 0; j < 4; j++) d[i][j] = 0.f;

    const int nT = 2 * kr + 1;      // B tiles (dy rows)
    const int nAt = taps * 2;       // A tiles (tap x {wh,wl})

    for (int kc = 0; kc < kcNum; kc++) {
        __syncthreads();            // previous-iteration consumers done
        // ---- stage B tiles [130 px][64 ci] (xh only) via cp.async
        const int totB = nT * 1040;
        for (int i = tid; i < totB; i += 256) {
            int tIdx = i / 1040, rem = i - tIdx * 1040;
            int row = rem >> 3, c16 = rem & 7;
            int px = row - 1;
            int hh = h + tIdx - kr;
            bool p = ((unsigned)px < Wc) && ((unsigned)hh < Hc);
            const __half* g = ah + (((size_t)b * Hc + hh) * Wc + px) * Cpad + kc * 64 + c16 * 8;
            cpa16(sB + tIdx * 16640 + SWZ(row * 128 + c16 * 16), p ? g : ah, p);
        }
        // ---- stage A tile 0 (tap 0, wh)
#pragma unroll
        for (int j = 0; j < 4; j++) {
            int i = tid + j * 256;
            int row = i >> 3, c16 = i & 7;
            cpa16(sA + SWZ(row * 128 + c16 * 16),
                  wgh + ((size_t)0 * coPad + mt * 128 + row) * Cpad + kc * 64 + c16 * 8, true);
        }
        cpa_commit();
        cpa_wait0();
        __syncthreads();

        for (int t = 0; t < nAt; t++) {
            // issue async copy of next A tile into alternate buffer
            if (t + 1 < nAt) {
                int tap = (t + 1) >> 1;
                const __half* ws = ((t + 1) & 1) ? wgl : wgh;
                const uint32_t dstA = sA + (uint32_t)((t + 1) & 1) * 16384u;
#pragma unroll
                for (int j = 0; j < 4; j++) {
                    int i = tid + j * 256;
                    int row = i >> 3, c16 = i & 7;
                    cpa16(dstA + SWZ(row * 128 + c16 * 16),
                          ws + ((size_t)tap * coPad + mt * 128 + row) * Cpad + kc * 64 + c16 * 8,
                          true);
                }
                cpa_commit();
            }
            // compute with current A buffer
            const int tap = t >> 1;
            const int dyI = tap / kw, dx = tap % kw - kr;
            const uint32_t Ab = sA + (uint32_t)(t & 1) * 16384u;
            const uint32_t Bt = sB + (uint32_t)(dyI * 16640);
#pragma unroll
            for (int ks = 0; ks < 4; ks++) {
                uint32_t a[2][4];
#pragma unroll
                for (int mi = 0; mi < 2; mi++) {
                    uint32_t ad = Ab + SWZ((uint32_t)((cbw + mi * 16 + ((midx & 1) << 3) + l7) * 128
                                                      + (2 * ks + (midx >> 1)) * 16));
                    ldsm4(a[mi], ad);
                }
                uint32_t bf[4][4];
#pragma unroll
                for (int np = 0; np < 4; np++) {
                    int brow = nbw + np * 16 + ((midx >> 1) << 3) + l7 + 1 + dx;
                    uint32_t bd = Bt + SWZ((uint32_t)(brow * 128 + (2 * ks + (midx & 1)) * 16));
                    ldsm4(bf[np], bd);
                }
#pragma unroll
                for (int mi = 0; mi < 2; mi++)
#pragma unroll
                    for (int ni = 0; ni < 8; ni++)
                        mma16816(d[mi * 8 + ni], a[mi],
                                 bf[ni >> 1][(ni & 1) * 2], bf[ni >> 1][(ni & 1) * 2 + 1]);
            }
            cpa_wait0();
            __syncthreads();
        }
    }

    // ---- epilogue: bias+relu, transpose through smem (B region reused)
    float bias4[4];
#pragma unroll
    for (int k2 = 0; k2 < 4; k2++) {
        int gco = mt * 128 + cbw + (k2 >> 1) * 16 + gid + (k2 & 1) * 8;
        bias4[k2] = (gco < coutUsed) ? bias[gco] : 0.f;
    }
    __syncthreads();

    if (of32) {
        // [co 128][px 128 + pad4] fp32 at sB
#pragma unroll
        for (int mi = 0; mi < 2; mi++)
#pragma unroll
            for (int ni = 0; ni < 8; ni++)
#pragma unroll
                for (int k = 0; k < 4; k++) {
                    int co = cbw + mi * 16 + gid + ((k >> 1) << 3);
                    int px = nbw + ni * 8 + 2 * tig + (k & 1);
                    float v = fmaxf(d[mi * 8 + ni][k] + bias4[mi * 2 + (k >> 1)], 0.f);
                    *reinterpret_cast<float*>(smem + 32768 + (co * 132 + px) * 4) = v;
                }
        __syncthreads();
        for (int i = tid; i < 128 * 32; i += 256) {
            int row = i >> 5, q = i & 31;
            if (mt * 128 + row < coutUsed) {
                uint4 v = *reinterpret_cast<uint4*>(smem + 32768 + (row * 132 + q * 4) * 4);
                *reinterpret_cast<uint4*>(
                    of32 + (((size_t)b * 128 + mt * 128 + row) * Hc + h) * Wc + q * 4) = v;
            }
        }
    } else {
        // [px 128][co 128 + pad8] fp16 at sB
#pragma unroll
        for (int mi = 0; mi < 2; mi++)
#pragma unroll
            for (int ni = 0; ni < 8; ni++)
#pragma unroll
                for (int k = 0; k < 4; k++) {
                    int co = cbw + mi * 16 + gid + ((k >> 1) << 3);
                    int px = nbw + ni * 8 + 2 * tig + (k & 1);
                    float v = fmaxf(d[mi * 8 + ni][k] + bias4[mi * 2 + (k >> 1)], 0.f);
                    *reinterpret_cast<__half*>(smem + 32768 + px * 272 + co * 2) = __float2half(v);
                }
        __syncthreads();
        for (int i = tid; i < 128 * 16; i += 256) {
            int row = i >> 4, q = i & 15;
            int gcoB = mt * 128 + q * 8;
            size_t dst = (((size_t)b * Hc + h) * Wc + row) * outCpad + outCoff + mt * 128 + q * 8;
            uint4 vh = *reinterpret_cast<uint4*>(smem + 32768 + row * 272 + q * 16);
            if (gcoB + 8 <= coutUsed) {
                *reinterpret_cast<uint4*>(oh + dst) = vh;
            } else if (gcoB < coutUsed) {
                const __half* ph = reinterpret_cast<const __half*>(&vh);
                for (int e = 0; e < coutUsed - gcoB; e++) oh[dst + e] = ph[e];
            }
        }
    }
}

// append flow into output channels 126..127 (NCHW fp32)
__global__ void concat_flow_k(const float* __restrict__ flow, float* __restrict__ out)
{
    int i = blockIdx.x * 256 + threadIdx.x;
    if (i < Bn * 2 * HW) {
        int b = i / (2 * HW);
        int r = i % (2 * HW);
        out[(size_t)b * 128 * HW + (size_t)126 * HW + r] = flow[i];
    }
}

// ---------------------------------------------------------------------------
extern "C" void kernel_launch(void* const* d_in, const int* in_sizes, int n_in,
                              void* d_out, int out_size)
{
    const float* flow = (const float*)d_in[0];
    const float* corr = (const float*)d_in[1];
    const float* wc1  = (const float*)d_in[2];
    const float* bc1  = (const float*)d_in[3];
    const float* wc2  = (const float*)d_in[4];
    const float* bc2  = (const float*)d_in[5];
    const float* wf1  = (const float*)d_in[6];
    const float* bf1  = (const float*)d_in[7];
    const float* wf2  = (const float*)d_in[8];
    const float* bf2  = (const float*)d_in[9];
    const float* wo   = (const float*)d_in[10];
    const float* bo   = (const float*)d_in[11];
    float* out = (float*)d_out;

    __half *corrh, *cor1h, *flo1h, *cath;
    __half *wc1h, *wc1l, *wc2h, *wc2l, *wf2h, *wf2l, *woh, *wol;
    cudaGetSymbolAddress((void**)&corrh, g_corr_h);
    cudaGetSymbolAddress((void**)&cor1h, g_cor1_h);
    cudaGetSymbolAddress((void**)&flo1h, g_flo1_h);
    cudaGetSymbolAddress((void**)&cath,  g_cat_h);
    cudaGetSymbolAddress((void**)&wc1h,  g_wc1_h);  cudaGetSymbolAddress((void**)&wc1l,  g_wc1_l);
    cudaGetSymbolAddress((void**)&wc2h,  g_wc2_h);  cudaGetSymbolAddress((void**)&wc2l,  g_wc2_l);
    cudaGetSymbolAddress((void**)&wf2h,  g_wf2_h);  cudaGetSymbolAddress((void**)&wf2l,  g_wf2_l);
    cudaGetSymbolAddress((void**)&woh,   g_wo_h);   cudaGetSymbolAddress((void**)&wol,   g_wo_l);

    cudaFuncSetAttribute(conv_mma_k, cudaFuncAttributeMaxDynamicSharedMemorySize, SMEM_BYTES);

    // prep
    wprep_k<<<128, 256>>>(wc1, 256, 324, 1, 256, 384, wc1h, wc1l);
    wprep_k<<<256, 256>>>(wc2, 192, 256, 9, 256, 256, wc2h, wc2l);
    wprep_k<<<128, 256>>>(wf2,  64, 128, 9, 128, 128, wf2h, wf2l);
    wprep_k<<<128, 256>>>(wo,  126, 256, 9, 128, 256, woh, wol);
    corr2nhwc_k<<<dim3(12, Hc, Bn), 256>>>(corr, corrh);

    // flo1 = relu(conv7x7(flow)) -> NHWC fp16 (Cpad 128)
    conv7x7_relu_k<<<dim3(Wc / 32, Hc / 8, Bn * 8), 256>>>(flow, wf1, bf1, flo1h);

    // cor1 = relu(conv1x1(corr))   [256ch, Cin 324->384]
    conv_mma_k<<<dim3(2, Hc, Bn), 256, SMEM_BYTES>>>(
        corrh, 384, 6, wc1h, wc1l, 256, bc1, 256, 1, 1, 0,
        cor1h, 256, 0, nullptr);
    // cat[:,0:192] = relu(conv3x3(cor1))
    conv_mma_k<<<dim3(2, Hc, Bn), 256, SMEM_BYTES>>>(
        cor1h, 256, 4, wc2h, wc2l, 256, bc2, 192, 9, 3, 1,
        cath, 256, 0, nullptr);
    // cat[:,192:256] = relu(conv3x3(flo1))
    conv_mma_k<<<dim3(1, Hc, Bn), 256, SMEM_BYTES>>>(
        flo1h, 128, 2, wf2h, wf2l, 128, bf2, 64, 9, 3, 1,
        cath, 256, 192, nullptr);
    // d_out[:,0:126] = relu(conv3x3(cat))  (fp32 NCHW)
    conv_mma_k<<<dim3(1, Hc, Bn), 256, SMEM_BYTES>>>(
        cath, 256, 4, woh, wol, 128, bo, 126, 9, 3, 1,
        nullptr, 128, 0, out);
    // d_out[:,126:128] = flow
    concat_flow_k<<<(Bn * 2 * HW + 255) / 256, 256>>>(flow, out);
}

// round 7
// speedup vs baseline: 4.3648x; 1.0743x over previous
#include <cuda_runtime.h>
#include <cuda_fp16.h>
#include <stdint.h>

#define Bn 8
#define Hc 96
#define Wc 128
#define HW (Hc*Wc)

// ---------------- scratch (__device__ globals; allocation-free rule) -------
__device__ __half g_corr_h[(size_t)Bn*HW*384];
__device__ __half g_cor1_h[(size_t)Bn*HW*256];
__device__ __half g_flo1_h[(size_t)Bn*HW*128];
__device__ __half g_cat_h [(size_t)Bn*HW*256];
__device__ __half g_wc1_h[1*256*384], g_wc1_l[1*256*384];
__device__ __half g_wc2_h[9*256*256], g_wc2_l[9*256*256];
__device__ __half g_wf2_h[9*128*128], g_wf2_l[9*128*128];
__device__ __half g_wo_h [9*128*256], g_wo_l [9*128*256];

// ---------------- helpers ---------------------------------------------------
__device__ __forceinline__ uint32_t s2u(const void* p) {
    uint32_t a;
    asm("{ .reg .u64 t; cvta.to.shared.u64 t, %1; cvt.u32.u64 %0, t; }"
        : "=r"(a) : "l"(p));
    return a;
}
#define SWZ(x) ((x) ^ (((x) >> 3) & 0x70))

__device__ __forceinline__ void ldsm4(uint32_t* r, uint32_t addr) {
    asm volatile("ldmatrix.sync.aligned.m8n8.x4.shared.b16 {%0,%1,%2,%3}, [%4];"
        : "=r"(r[0]), "=r"(r[1]), "=r"(r[2]), "=r"(r[3]) : "r"(addr));
}
__device__ __forceinline__ void mma16816(float* d, const uint32_t* a,
                                          uint32_t b0, uint32_t b1) {
    asm volatile(
        "mma.sync.aligned.m16n8k16.row.col.f32.f16.f16.f32 "
        "{%0,%1,%2,%3}, {%4,%5,%6,%7}, {%8,%9}, {%0,%1,%2,%3};"
        : "+f"(d[0]), "+f"(d[1]), "+f"(d[2]), "+f"(d[3])
        : "r"(a[0]), "r"(a[1]), "r"(a[2]), "r"(a[3]), "r"(b0), "r"(b1));
}
__device__ __forceinline__ void cpa16(uint32_t s, const void* g, bool p) {
    asm volatile("cp.async.ca.shared.global [%0], [%1], 16, %2;"
        :: "r"(s), "l"(g), "r"(p ? 16u : 0u));
}
__device__ __forceinline__ void cpa_commit() {
    asm volatile("cp.async.commit_group;" ::: "memory");
}
__device__ __forceinline__ void cpa_wait0() {
    asm volatile("cp.async.wait_group 0;" ::: "memory");
}

// ---------------- weight prep: OIHW fp32 -> [tap][coPad][Cpad] fp16 hi/lo ---
__global__ void wprep_k(const float* __restrict__ w, int cout, int cin, int taps,
                        int coPad, int Cpad,
                        __half* __restrict__ wh, __half* __restrict__ wl)
{
    size_t total = (size_t)taps * coPad * Cpad;
    for (size_t i = (size_t)blockIdx.x * blockDim.x + threadIdx.x; i < total;
         i += (size_t)gridDim.x * blockDim.x) {
        int ci = (int)(i % Cpad);
        size_t t = i / Cpad;
        int co = (int)(t % coPad);
        int tap = (int)(t / coPad);
        float v = 0.f;
        if (co < cout && ci < cin)
            v = w[((size_t)co * cin + ci) * taps + tap];
        __half h = __float2half(v);
        wh[i] = h;
        wl[i] = __float2half(v - __half2float(h));
    }
}

// ---------------- corr NCHW fp32 -> NHWC fp16 (Cpad=384, zero pad) ----------
__global__ __launch_bounds__(256) void corr2nhwc_k(
    const float* __restrict__ corr, __half* __restrict__ oh)
{
    const int c0 = blockIdx.x * 32, h = blockIdx.y, b = blockIdx.z;
    __shared__ float t[32][129];
    for (int i = threadIdx.x; i < 32 * 128; i += 256) {
        int ci = i >> 7, px = i & 127;
        float v = 0.f;
        if (c0 + ci < 324)
            v = corr[((size_t)b * 324 + c0 + ci) * HW + h * Wc + px];
        t[ci][px] = v;
    }
    __syncthreads();
    for (int i = threadIdx.x; i < 32 * 128; i += 256) {
        int px = i >> 5, ci = i & 31;
        size_t o = (((size_t)b * Hc + h) * Wc + px) * 384 + c0 + ci;
        oh[o] = __float2half(t[ci][px]);
    }
}

// ---------------- conv7x7 (Cin=2, Cout=128) fp32 -> NHWC fp16 ---------------
__global__ __launch_bounds__(256) void conv7x7_relu_k(
    const float* __restrict__ in, const float* __restrict__ w,
    const float* __restrict__ bias, __half* __restrict__ oh)
{
    const int tid = threadIdx.x;
    const int tx = tid & 31, ty = tid >> 5;
    const int w0 = blockIdx.x * 32, h0 = blockIdx.y * 8;
    const int coTile = blockIdx.z & 7;
    const int b = blockIdx.z >> 3;
    const int coBase = coTile * 16;

    __shared__ float st[2][14][38];
    __shared__ float sw[16 * 2 * 49];

    const float* inb = in + (size_t)b * 2 * HW;
    for (int i = tid; i < 2 * 14 * 38; i += 256) {
        int ci = i / 532, r = (i % 532) / 38, c = i % 38;
        int hh = h0 + r - 3, ww = w0 + c - 3;
        float v = 0.f;
        if ((unsigned)hh < Hc && (unsigned)ww < Wc)
            v = inb[(size_t)ci * HW + hh * Wc + ww];
        st[ci][r][c] = v;
    }
    for (int i = tid; i < 1568; i += 256)
        sw[i] = w[(size_t)coBase * 98 + i];
    __syncthreads();

    float acc[16];
#pragma unroll
    for (int i = 0; i < 16; i++) acc[i] = 0.f;

#pragma unroll
    for (int ci = 0; ci < 2; ci++)
#pragma unroll
        for (int dy = 0; dy < 7; dy++) {
            float xv[7];
#pragma unroll
            for (int k = 0; k < 7; k++) xv[k] = st[ci][ty + dy][tx + k];
#pragma unroll
            for (int co = 0; co < 16; co++)
#pragma unroll
                for (int dx = 0; dx < 7; dx++)
                    acc[co] = fmaf(sw[co * 98 + ci * 49 + dy * 7 + dx], xv[dx], acc[co]);
        }

    const int hh = h0 + ty, ww = w0 + tx;
    __align__(16) __half vh[16];
#pragma unroll
    for (int co = 0; co < 16; co++)
        vh[co] = __float2half(fmaxf(acc[co] + bias[coBase + co], 0.f));
    size_t base = (((size_t)b * Hc + hh) * Wc + ww) * 128 + coBase;
    reinterpret_cast<uint4*>(oh + base)[0] = reinterpret_cast<uint4*>(vh)[0];
    reinterpret_cast<uint4*>(oh + base)[1] = reinterpret_cast<uint4*>(vh)[1];
}

// ---------------- HMMA conv-as-GEMM (tap-paired wh/wl, shared B frags) ------
// Block: 256 thr / 8 warps; out tile 128co x 128px (one image row).
// A: 3-slot ring (3x16KB); tap t occupies slots (2t)%3,(2t+1)%3 (wh,wl).
// Per ks: load B frags ONCE, mma with wh then wl (B ldsm halved vs R5).
// B: (2kr+1) x [130px][64ci] tiles per kc, reused by all taps.
// smem: A 49152 @0 ; B 49920 @49152 (region reused by epilogue).
#define SMEM_BYTES 99072

__global__ __launch_bounds__(256, 2) void conv_mma_k(
    const __half* __restrict__ ah, int Cpad, int kcNum,
    const __half* __restrict__ wgh, const __half* __restrict__ wgl,
    int coPad, const float* __restrict__ bias, int coutUsed,
    int taps, int kw, int kr,
    __half* __restrict__ oh, int outCpad, int outCoff,
    float* __restrict__ of32)
{
    extern __shared__ __align__(16) char smem[];
    const uint32_t sA = s2u(smem);
    const uint32_t sB = sA + 49152u;

    const int tid = threadIdx.x;
    const int warp = tid >> 5, lane = tid & 31;
    const int mt = blockIdx.x, h = blockIdx.y, b = blockIdx.z;
    const int cbw = (warp >> 1) * 32;
    const int nbw = (warp & 1) * 64;
    const int gid = lane >> 2, tig = lane & 3;
    const int midx = lane >> 3, l7 = lane & 7;

    float d[16][4];
#pragma unroll
    for (int i = 0; i < 16; i++)
#pragma unroll
        for (int j = 0; j < 4; j++) d[i][j] = 0.f;

    const int nT = 2 * kr + 1;

    // stage one A subtile (tap, ws already offset by kc) into ring slot
    auto stageA = [&](int tap, const __half* ws, int slot) {
        const uint32_t dst = sA + (uint32_t)slot * 16384u;
#pragma unroll
        for (int j = 0; j < 4; j++) {
            int i = tid + j * 256;
            int row = i >> 3, c16 = i & 7;
            cpa16(dst + SWZ(row * 128 + c16 * 16),
                  ws + ((size_t)tap * coPad + mt * 128 + row) * Cpad + c16 * 8, true);
        }
    };

    for (int kc = 0; kc < kcNum; kc++) {
        const size_t kcOff = (size_t)kc * 64;
        const __half* wH = wgh + kcOff;
        const __half* wL = wgl + kcOff;
        __syncthreads();
        // ---- stage B tiles [130 px][64 ci] via cp.async
        const int totB = nT * 1040;
        for (int i = tid; i < totB; i += 256) {
            int tIdx = i / 1040, rem = i - tIdx * 1040;
            int row = rem >> 3, c16 = rem & 7;
            int px = row - 1;
            int hh = h + tIdx - kr;
            bool p = ((unsigned)px < Wc) && ((unsigned)hh < Hc);
            const __half* g = ah + (((size_t)b * Hc + hh) * Wc + px) * Cpad + kcOff + c16 * 8;
            cpa16(sB + tIdx * 16640 + SWZ(row * 128 + c16 * 16), p ? g : ah, p);
        }
        // ---- stage A pair of tap 0 (slots 0, 1)
        stageA(0, wH, 0);
        stageA(0, wL, 1);
        cpa_commit();
        cpa_wait0();
        __syncthreads();

        for (int tap = 0; tap < taps; tap++) {
            // overlap: prefetch wh of next tap into the free ring slot
            if (tap + 1 < taps) {
                stageA(tap + 1, wH, (2 * tap + 2) % 3);
                cpa_commit();
            }
            const int dyI = tap / kw, dx = tap % kw - kr;
            const uint32_t A0 = sA + (uint32_t)(((2 * tap)     % 3) * 16384);
            const uint32_t A1 = sA + (uint32_t)(((2 * tap + 1) % 3) * 16384);
            const uint32_t Bt = sB + (uint32_t)(dyI * 16640);
#pragma unroll
            for (int ks = 0; ks < 4; ks++) {
                uint32_t bf[4][4];
#pragma unroll
                for (int np = 0; np < 4; np++) {
                    int brow = nbw + np * 16 + ((midx >> 1) << 3) + l7 + 1 + dx;
                    uint32_t bd = Bt + SWZ((uint32_t)(brow * 128 + (2 * ks + (midx & 1)) * 16));
                    ldsm4(bf[np], bd);
                }
                const uint32_t aoff = SWZ((uint32_t)((cbw + ((midx & 1) << 3) + l7) * 128
                                                     + (2 * ks + (midx >> 1)) * 16));
                const uint32_t aoff2 = SWZ((uint32_t)((cbw + 16 + ((midx & 1) << 3) + l7) * 128
                                                      + (2 * ks + (midx >> 1)) * 16));
                uint32_t a[2][4];
                ldsm4(a[0], A0 + aoff);
                ldsm4(a[1], A0 + aoff2);
#pragma unroll
                for (int mi = 0; mi < 2; mi++)
#pragma unroll
                    for (int ni = 0; ni < 8; ni++)
                        mma16816(d[mi * 8 + ni], a[mi],
                                 bf[ni >> 1][(ni & 1) * 2], bf[ni >> 1][(ni & 1) * 2 + 1]);
                ldsm4(a[0], A1 + aoff);
                ldsm4(a[1], A1 + aoff2);
#pragma unroll
                for (int mi = 0; mi < 2; mi++)
#pragma unroll
                    for (int ni = 0; ni < 8; ni++)
                        mma16816(d[mi * 8 + ni], a[mi],
                                 bf[ni >> 1][(ni & 1) * 2], bf[ni >> 1][(ni & 1) * 2 + 1]);
            }
            __syncthreads();              // all warps done with slot (2tap)%3
            if (tap + 1 < taps) {
                stageA(tap + 1, wL, (2 * tap) % 3);   // wl of next tap
                cpa_commit();
                cpa_wait0();
                __syncthreads();
            }
        }
    }

    // ---- epilogue: bias+relu, transpose through smem (B region reused)
    float bias4[4];
#pragma unroll
    for (int k2 = 0; k2 < 4; k2++) {
        int gco = mt * 128 + cbw + (k2 >> 1) * 16 + gid + (k2 & 1) * 8;
        bias4[k2] = (gco < coutUsed) ? bias[gco] : 0.f;
    }
    __syncthreads();

    if (of32) {
        // two passes of 64 co: [64co][128px + pad4] fp32 at sB (33792 B)
        for (int p = 0; p < 2; p++) {
            if ((cbw >> 6) == p) {
#pragma unroll
                for (int mi = 0; mi < 2; mi++)
#pragma unroll
                    for (int ni = 0; ni < 8; ni++)
#pragma unroll
                        for (int k = 0; k < 4; k++) {
                            int co = (cbw & 63) + mi * 16 + gid + ((k >> 1) << 3);
                            int px = nbw + ni * 8 + 2 * tig + (k & 1);
                            float v = fmaxf(d[mi * 8 + ni][k] + bias4[mi * 2 + (k >> 1)], 0.f);
                            *reinterpret_cast<float*>(smem + 49152 + (co * 132 + px) * 4) = v;
                        }
            }
            __syncthreads();
            for (int i = tid; i < 64 * 32; i += 256) {
                int row = i >> 5, q = i & 31;
                int gco = mt * 128 + p * 64 + row;
                if (gco < coutUsed) {
                    uint4 v = *reinterpret_cast<uint4*>(smem + 49152 + (row * 132 + q * 4) * 4);
                    *reinterpret_cast<uint4*>(
                        of32 + (((size_t)b * 128 + gco) * Hc + h) * Wc + q * 4) = v;
                }
            }
            __syncthreads();
        }
    } else {
        // [px 128][co 128 + pad8] fp16 at sB (34816 B)
#pragma unroll
        for (int mi = 0; mi < 2; mi++)
#pragma unroll
            for (int ni = 0; ni < 8; ni++)
#pragma unroll
                for (int k = 0; k < 4; k++) {
                    int co = cbw + mi * 16 + gid + ((k >> 1) << 3);
                    int px = nbw + ni * 8 + 2 * tig + (k & 1);
                    float v = fmaxf(d[mi * 8 + ni][k] + bias4[mi * 2 + (k >> 1)], 0.f);
                    *reinterpret_cast<__half*>(smem + 49152 + px * 272 + co * 2) = __float2half(v);
                }
        __syncthreads();
        for (int i = tid; i < 128 * 16; i += 256) {
            int row = i >> 4, q = i & 15;
            int gcoB = mt * 128 + q * 8;
            size_t dst = (((size_t)b * Hc + h) * Wc + row) * outCpad + outCoff + mt * 128 + q * 8;
            uint4 vh = *reinterpret_cast<uint4*>(smem + 49152 + row * 272 + q * 16);
            if (gcoB + 8 <= coutUsed) {
                *reinterpret_cast<uint4*>(oh + dst) = vh;
            } else if (gcoB < coutUsed) {
                const __half* ph = reinterpret_cast<const __half*>(&vh);
                for (int e = 0; e < coutUsed - gcoB; e++) oh[dst + e] = ph[e];
            }
        }
    }
}

// append flow into output channels 126..127 (NCHW fp32)
__global__ void concat_flow_k(const float* __restrict__ flow, float* __restrict__ out)
{
    int i = blockIdx.x * 256 + threadIdx.x;
    if (i < Bn * 2 * HW) {
        int b = i / (2 * HW);
        int r = i % (2 * HW);
        out[(size_t)b * 128 * HW + (size_t)126 * HW + r] = flow[i];
    }
}

// ---------------------------------------------------------------------------
extern "C" void kernel_launch(void* const* d_in, const int* in_sizes, int n_in,
                              void* d_out, int out_size)
{
    const float* flow = (const float*)d_in[0];
    const float* corr = (const float*)d_in[1];
    const float* wc1  = (const float*)d_in[2];
    const float* bc1  = (const float*)d_in[3];
    const float* wc2  = (const float*)d_in[4];
    const float* bc2  = (const float*)d_in[5];
    const float* wf1  = (const float*)d_in[6];
    const float* bf1  = (const float*)d_in[7];
    const float* wf2  = (const float*)d_in[8];
    const float* bf2  = (const float*)d_in[9];
    const float* wo   = (const float*)d_in[10];
    const float* bo   = (const float*)d_in[11];
    float* out = (float*)d_out;

    __half *corrh, *cor1h, *flo1h, *cath;
    __half *wc1h, *wc1l, *wc2h, *wc2l, *wf2h, *wf2l, *woh, *wol;
    cudaGetSymbolAddress((void**)&corrh, g_corr_h);
    cudaGetSymbolAddress((void**)&cor1h, g_cor1_h);
    cudaGetSymbolAddress((void**)&flo1h, g_flo1_h);
    cudaGetSymbolAddress((void**)&cath,  g_cat_h);
    cudaGetSymbolAddress((void**)&wc1h,  g_wc1_h);  cudaGetSymbolAddress((void**)&wc1l,  g_wc1_l);
    cudaGetSymbolAddress((void**)&wc2h,  g_wc2_h);  cudaGetSymbolAddress((void**)&wc2l,  g_wc2_l);
    cudaGetSymbolAddress((void**)&wf2h,  g_wf2_h);  cudaGetSymbolAddress((void**)&wf2l,  g_wf2_l);
    cudaGetSymbolAddress((void**)&woh,   g_wo_h);   cudaGetSymbolAddress((void**)&wol,   g_wo_l);

    cudaFuncSetAttribute(conv_mma_k, cudaFuncAttributeMaxDynamicSharedMemorySize, SMEM_BYTES);

    // prep
    wprep_k<<<128, 256>>>(wc1, 256, 324, 1, 256, 384, wc1h, wc1l);
    wprep_k<<<256, 256>>>(wc2, 192, 256, 9, 256, 256, wc2h, wc2l);
    wprep_k<<<128, 256>>>(wf2,  64, 128, 9, 128, 128, wf2h, wf2l);
    wprep_k<<<128, 256>>>(wo,  126, 256, 9, 128, 256, woh, wol);
    corr2nhwc_k<<<dim3(12, Hc, Bn), 256>>>(corr, corrh);

    // flo1 = relu(conv7x7(flow)) -> NHWC fp16 (Cpad 128)
    conv7x7_relu_k<<<dim3(Wc / 32, Hc / 8, Bn * 8), 256>>>(flow, wf1, bf1, flo1h);

    // cor1 = relu(conv1x1(corr))   [256ch, Cin 324->384]
    conv_mma_k<<<dim3(2, Hc, Bn), 256, SMEM_BYTES>>>(
        corrh, 384, 6, wc1h, wc1l, 256, bc1, 256, 1, 1, 0,
        cor1h, 256, 0, nullptr);
    // cat[:,0:192] = relu(conv3x3(cor1))
    conv_mma_k<<<dim3(2, Hc, Bn), 256, SMEM_BYTES>>>(
        cor1h, 256, 4, wc2h, wc2l, 256, bc2, 192, 9, 3, 1,
        cath, 256, 0, nullptr);
    // cat[:,192:256] = relu(conv3x3(flo1))
    conv_mma_k<<<dim3(1, Hc, Bn), 256, SMEM_BYTES>>>(
        flo1h, 128, 2, wf2h, wf2l, 128, bf2, 64, 9, 3, 1,
        cath, 256, 192, nullptr);
    // d_out[:,0:126] = relu(conv3x3(cat))  (fp32 NCHW)
    conv_mma_k<<<dim3(1, Hc, Bn), 256, SMEM_BYTES>>>(
        cath, 256, 4, woh, wol, 128, bo, 126, 9, 3, 1,
        nullptr, 128, 0, out);
    // d_out[:,126:128] = flow
    concat_flow_k<<<(Bn * 2 * HW + 255) / 256, 256>>>(flow, out);
}

// round 8
// speedup vs baseline: 4.4910x; 1.0289x over previous
#include <cuda_runtime.h>
#include <cuda_fp16.h>
#include <stdint.h>

#define Bn 8
#define Hc 96
#define Wc 128
#define HW (Hc*Wc)

// ---------------- scratch (__device__ globals; allocation-free rule) -------
__device__ __half g_corr_h[(size_t)Bn*HW*384];
__device__ __half g_cor1_h[(size_t)Bn*HW*256];
__device__ __half g_flo1_h[(size_t)Bn*HW*128];
__device__ __half g_cat_h [(size_t)Bn*HW*256];
__device__ __half g_wc1_h[1*256*384], g_wc1_l[1*256*384];
__device__ __half g_wc2_h[9*256*256], g_wc2_l[9*256*256];
__device__ __half g_wf2_h[9*128*128], g_wf2_l[9*128*128];
__device__ __half g_wo_h [9*128*256], g_wo_l [9*128*256];

// ---------------- helpers ---------------------------------------------------
__device__ __forceinline__ uint32_t s2u(const void* p) {
    uint32_t a;
    asm("{ .reg .u64 t; cvta.to.shared.u64 t, %1; cvt.u32.u64 %0, t; }"
        : "=r"(a) : "l"(p));
    return a;
}
#define SWZ(x) ((x) ^ (((x) >> 3) & 0x70))

__device__ __forceinline__ void ldsm4(uint32_t* r, uint32_t addr) {
    asm volatile("ldmatrix.sync.aligned.m8n8.x4.shared.b16 {%0,%1,%2,%3}, [%4];"
        : "=r"(r[0]), "=r"(r[1]), "=r"(r[2]), "=r"(r[3]) : "r"(addr));
}
__device__ __forceinline__ void mma16816(float* d, const uint32_t* a,
                                          uint32_t b0, uint32_t b1) {
    asm volatile(
        "mma.sync.aligned.m16n8k16.row.col.f32.f16.f16.f32 "
        "{%0,%1,%2,%3}, {%4,%5,%6,%7}, {%8,%9}, {%0,%1,%2,%3};"
        : "+f"(d[0]), "+f"(d[1]), "+f"(d[2]), "+f"(d[3])
        : "r"(a[0]), "r"(a[1]), "r"(a[2]), "r"(a[3]), "r"(b0), "r"(b1));
}
__device__ __forceinline__ void cpa16(uint32_t s, const void* g, bool p) {
    asm volatile("cp.async.ca.shared.global [%0], [%1], 16, %2;"
        :: "r"(s), "l"(g), "r"(p ? 16u : 0u));
}
__device__ __forceinline__ void cpa_commit() {
    asm volatile("cp.async.commit_group;" ::: "memory");
}
__device__ __forceinline__ void cpa_wait0() {
    asm volatile("cp.async.wait_group 0;" ::: "memory");
}

// ---------------- weight prep: OIHW fp32 -> [tap][coPad][Cpad] fp16 hi/lo ---
__global__ void wprep_k(const float* __restrict__ w, int cout, int cin, int taps,
                        int coPad, int Cpad,
                        __half* __restrict__ wh, __half* __restrict__ wl)
{
    size_t total = (size_t)taps * coPad * Cpad;
    for (size_t i = (size_t)blockIdx.x * blockDim.x + threadIdx.x; i < total;
         i += (size_t)gridDim.x * blockDim.x) {
        int ci = (int)(i % Cpad);
        size_t t = i / Cpad;
        int co = (int)(t % coPad);
        int tap = (int)(t / coPad);
        float v = 0.f;
        if (co < cout && ci < cin)
            v = w[((size_t)co * cin + ci) * taps + tap];
        __half h = __float2half(v);
        wh[i] = h;
        wl[i] = __float2half(v - __half2float(h));
    }
}

// ---------------- corr NCHW fp32 -> NHWC fp16 (Cpad=384, zero pad) ----------
__global__ __launch_bounds__(256) void corr2nhwc_k(
    const float* __restrict__ corr, __half* __restrict__ oh)
{
    const int c0 = blockIdx.x * 32, h = blockIdx.y, b = blockIdx.z;
    __shared__ float t[32][129];
    for (int i = threadIdx.x; i < 32 * 128; i += 256) {
        int ci = i >> 7, px = i & 127;
        float v = 0.f;
        if (c0 + ci < 324)
            v = corr[((size_t)b * 324 + c0 + ci) * HW + h * Wc + px];
        t[ci][px] = v;
    }
    __syncthreads();
    for (int i = threadIdx.x; i < 32 * 128; i += 256) {
        int px = i >> 5, ci = i & 31;
        size_t o = (((size_t)b * Hc + h) * Wc + px) * 384 + c0 + ci;
        oh[o] = __float2half(t[ci][px]);
    }
}

// ---------------- conv7x7 (Cin=2, Cout=128) fp32 -> NHWC fp16 ---------------
__global__ __launch_bounds__(256) void conv7x7_relu_k(
    const float* __restrict__ in, const float* __restrict__ w,
    const float* __restrict__ bias, __half* __restrict__ oh)
{
    const int tid = threadIdx.x;
    const int tx = tid & 31, ty = tid >> 5;
    const int w0 = blockIdx.x * 32, h0 = blockIdx.y * 8;
    const int coTile = blockIdx.z & 7;
    const int b = blockIdx.z >> 3;
    const int coBase = coTile * 16;

    __shared__ float st[2][14][38];
    __shared__ float sw[16 * 2 * 49];

    const float* inb = in + (size_t)b * 2 * HW;
    for (int i = tid; i < 2 * 14 * 38; i += 256) {
        int ci = i / 532, r = (i % 532) / 38, c = i % 38;
        int hh = h0 + r - 3, ww = w0 + c - 3;
        float v = 0.f;
        if ((unsigned)hh < Hc && (unsigned)ww < Wc)
            v = inb[(size_t)ci * HW + hh * Wc + ww];
        st[ci][r][c] = v;
    }
    for (int i = tid; i < 1568; i += 256)
        sw[i] = w[(size_t)coBase * 98 + i];
    __syncthreads();

    float acc[16];
#pragma unroll
    for (int i = 0; i < 16; i++) acc[i] = 0.f;

#pragma unroll
    for (int ci = 0; ci < 2; ci++)
#pragma unroll
        for (int dy = 0; dy < 7; dy++) {
            float xv[7];
#pragma unroll
            for (int k = 0; k < 7; k++) xv[k] = st[ci][ty + dy][tx + k];
#pragma unroll
            for (int co = 0; co < 16; co++)
#pragma unroll
                for (int dx = 0; dx < 7; dx++)
                    acc[co] = fmaf(sw[co * 98 + ci * 49 + dy * 7 + dx], xv[dx], acc[co]);
        }

    const int hh = h0 + ty, ww = w0 + tx;
    __align__(16) __half vh[16];
#pragma unroll
    for (int co = 0; co < 16; co++)
        vh[co] = __float2half(fmaxf(acc[co] + bias[coBase + co], 0.f));
    size_t base = (((size_t)b * Hc + hh) * Wc + ww) * 128 + coBase;
    reinterpret_cast<uint4*>(oh + base)[0] = reinterpret_cast<uint4*>(vh)[0];
    reinterpret_cast<uint4*>(oh + base)[1] = reinterpret_cast<uint4*>(vh)[1];
}

// ---------------- HMMA conv-as-GEMM (single-sync pipeline) ------------------
// Block: 256 thr / 8 warps; out tile 128co x 128px (one image row).
// A: 4-slot ring (step parity picks pair {2p,2p+1} = {wh,wl}); next step's
//    pair staged via cp.async during current compute.
// B: 2-slot ring of [130px][64ci] tiles; tile for dy-group G+1 prefetched at
//    the first step of group G. One commit + wait + sync per step.
// smem: A 65536 @0 ; B 2x16640 @65536. Epilogue reuses A region.
#define SMEM_BYTES 98816

__global__ __launch_bounds__(256, 2) void conv_mma_k(
    const __half* __restrict__ ah, int Cpad, int kcNum,
    const __half* __restrict__ wgh, const __half* __restrict__ wgl,
    int coPad, const float* __restrict__ bias, int coutUsed,
    int taps, int kw, int kr,
    __half* __restrict__ oh, int outCpad, int outCoff,
    float* __restrict__ of32)
{
    extern __shared__ __align__(16) char smem[];
    const uint32_t sA = s2u(smem);
    const uint32_t sB = sA + 65536u;

    const int tid = threadIdx.x;
    const int warp = tid >> 5, lane = tid & 31;
    const int mt = blockIdx.x, h = blockIdx.y, b = blockIdx.z;
    const int cbw = (warp >> 1) * 32;
    const int nbw = (warp & 1) * 64;
    const int gid = lane >> 2, tig = lane & 3;
    const int midx = lane >> 3, l7 = lane & 7;

    float d[16][4];
#pragma unroll
    for (int i = 0; i < 16; i++)
#pragma unroll
        for (int j = 0; j < 4; j++) d[i][j] = 0.f;

    const int nsteps = kcNum * taps;
    const int nG = kcNum * kw;          // dy-groups (kh == kw, square kernels)

    // stage A pair (wh,wl) for step s into slot pair {2(s&1), 2(s&1)+1}
    auto stageApair = [&](int s) {
        const int kcs = s / taps, tp = s % taps;
        const __half* wH = wgh + (size_t)kcs * 64;
        const __half* wL = wgl + (size_t)kcs * 64;
        const uint32_t d0 = sA + (uint32_t)((s & 1) * 2) * 16384u;
#pragma unroll
        for (int j = 0; j < 4; j++) {
            int i = tid + j * 256;
            int row = i >> 3, c16 = i & 7;
            size_t o = ((size_t)tp * coPad + mt * 128 + row) * Cpad + c16 * 8;
            uint32_t so = SWZ((uint32_t)(row * 128 + c16 * 16));
            cpa16(d0 + so, wH + o, true);
            cpa16(d0 + 16384u + so, wL + o, true);
        }
    };
    // stage B tile for dy-group G into slot G&1
    auto stageB = [&](int G) {
        const int kcs = G / kw, dyRow = G % kw;
        const int hh = h + dyRow - kr;
        const uint32_t dst = sB + (uint32_t)(G & 1) * 16640u;
        for (int i = tid; i < 1040; i += 256) {
            int row = i >> 3, c16 = i & 7;
            int px = row - 1;
            bool p = ((unsigned)px < Wc) && ((unsigned)hh < Hc);
            const __half* g = ah + (((size_t)b * Hc + hh) * Wc + px) * Cpad
                            + kcs * 64 + c16 * 8;
            cpa16(dst + SWZ(row * 128 + c16 * 16), p ? g : ah, p);
        }
    };

    // prologue: step 0 data
    stageB(0);
    stageApair(0);
    cpa_commit();
    cpa_wait0();
    __syncthreads();

    for (int s = 0; s < nsteps; s++) {
        const int kc = s / taps, tap = s % taps;
        const int dyI = tap / kw, dx = tap % kw - kr;
        const int G = kc * kw + dyI;

        // prefetch next step's A pair and (at group start) next B tile
        if (s + 1 < nsteps) stageApair(s + 1);
        if (tap % kw == 0 && G + 1 < nG) stageB(G + 1);
        cpa_commit();

        const uint32_t A0 = sA + (uint32_t)((s & 1) * 2) * 16384u;
        const uint32_t A1 = A0 + 16384u;
        const uint32_t Bt = sB + (uint32_t)(G & 1) * 16640u;
#pragma unroll
        for (int ks = 0; ks < 4; ks++) {
            uint32_t bf[4][4];
#pragma unroll
            for (int np = 0; np < 4; np++) {
                int brow = nbw + np * 16 + ((midx >> 1) << 3) + l7 + 1 + dx;
                uint32_t bd = Bt + SWZ((uint32_t)(brow * 128 + (2 * ks + (midx & 1)) * 16));
                ldsm4(bf[np], bd);
            }
            const uint32_t aoff = SWZ((uint32_t)((cbw + ((midx & 1) << 3) + l7) * 128
                                                 + (2 * ks + (midx >> 1)) * 16));
            const uint32_t aoff2 = SWZ((uint32_t)((cbw + 16 + ((midx & 1) << 3) + l7) * 128
                                                  + (2 * ks + (midx >> 1)) * 16));
            uint32_t a[2][4];
            ldsm4(a[0], A0 + aoff);
            ldsm4(a[1], A0 + aoff2);
#pragma unroll
            for (int mi = 0; mi < 2; mi++)
#pragma unroll
                for (int ni = 0; ni < 8; ni++)
                    mma16816(d[mi * 8 + ni], a[mi],
                             bf[ni >> 1][(ni & 1) * 2], bf[ni >> 1][(ni & 1) * 2 + 1]);
            ldsm4(a[0], A1 + aoff);
            ldsm4(a[1], A1 + aoff2);
#pragma unroll
            for (int mi = 0; mi < 2; mi++)
#pragma unroll
                for (int ni = 0; ni < 8; ni++)
                    mma16816(d[mi * 8 + ni], a[mi],
                             bf[ni >> 1][(ni & 1) * 2], bf[ni >> 1][(ni & 1) * 2 + 1]);
        }
        cpa_wait0();
        __syncthreads();
    }

    // ---- epilogue: bias+relu, transpose through smem (A region reused)
    float bias4[4];
#pragma unroll
    for (int k2 = 0; k2 < 4; k2++) {
        int gco = mt * 128 + cbw + (k2 >> 1) * 16 + gid + (k2 & 1) * 8;
        bias4[k2] = (gco < coutUsed) ? bias[gco] : 0.f;
    }

    if (of32) {
        // [128co][128px + pad4] fp32 at smem+0 (67584 B)
#pragma unroll
        for (int mi = 0; mi < 2; mi++)
#pragma unroll
            for (int ni = 0; ni < 8; ni++)
#pragma unroll
                for (int k = 0; k < 4; k++) {
                    int co = cbw + mi * 16 + gid + ((k >> 1) << 3);
                    int px = nbw + ni * 8 + 2 * tig + (k & 1);
                    float v = fmaxf(d[mi * 8 + ni][k] + bias4[mi * 2 + (k >> 1)], 0.f);
                    *reinterpret_cast<float*>(smem + (co * 132 + px) * 4) = v;
                }
        __syncthreads();
        for (int i = tid; i < 128 * 32; i += 256) {
            int row = i >> 5, q = i & 31;
            int gco = mt * 128 + row;
            if (gco < coutUsed) {
                uint4 v = *reinterpret_cast<uint4*>(smem + (row * 132 + q * 4) * 4);
                *reinterpret_cast<uint4*>(
                    of32 + (((size_t)b * 128 + gco) * Hc + h) * Wc + q * 4) = v;
            }
        }
    } else {
        // [px 128][co 128 + pad8] fp16 at smem+0 (34816 B)
#pragma unroll
        for (int mi = 0; mi < 2; mi++)
#pragma unroll
            for (int ni = 0; ni < 8; ni++)
#pragma unroll
                for (int k = 0; k < 4; k++) {
                    int co = cbw + mi * 16 + gid + ((k >> 1) << 3);
                    int px = nbw + ni * 8 + 2 * tig + (k & 1);
                    float v = fmaxf(d[mi * 8 + ni][k] + bias4[mi * 2 + (k >> 1)], 0.f);
                    *reinterpret_cast<__half*>(smem + px * 272 + co * 2) = __float2half(v);
                }
        __syncthreads();
        for (int i = tid; i < 128 * 16; i += 256) {
            int row = i >> 4, q = i & 15;
            int gcoB = mt * 128 + q * 8;
            size_t dst = (((size_t)b * Hc + h) * Wc + row) * outCpad + outCoff + mt * 128 + q * 8;
            uint4 vh = *reinterpret_cast<uint4*>(smem + row * 272 + q * 16);
            if (gcoB + 8 <= coutUsed) {
                *reinterpret_cast<uint4*>(oh + dst) = vh;
            } else if (gcoB < coutUsed) {
                const __half* ph = reinterpret_cast<const __half*>(&vh);
                for (int e = 0; e < coutUsed - gcoB; e++) oh[dst + e] = ph[e];
            }
        }
    }
}

// append flow into output channels 126..127 (NCHW fp32)
__global__ void concat_flow_k(const float* __restrict__ flow, float* __restrict__ out)
{
    int i = blockIdx.x * 256 + threadIdx.x;
    if (i < Bn * 2 * HW) {
        int b = i / (2 * HW);
        int r = i % (2 * HW);
        out[(size_t)b * 128 * HW + (size_t)126 * HW + r] = flow[i];
    }
}

// ---------------------------------------------------------------------------
extern "C" void kernel_launch(void* const* d_in, const int* in_sizes, int n_in,
                              void* d_out, int out_size)
{
    const float* flow = (const float*)d_in[0];
    const float* corr = (const float*)d_in[1];
    const float* wc1  = (const float*)d_in[2];
    const float* bc1  = (const float*)d_in[3];
    const float* wc2  = (const float*)d_in[4];
    const float* bc2  = (const float*)d_in[5];
    const float* wf1  = (const float*)d_in[6];
    const float* bf1  = (const float*)d_in[7];
    const float* wf2  = (const float*)d_in[8];
    const float* bf2  = (const float*)d_in[9];
    const float* wo   = (const float*)d_in[10];
    const float* bo   = (const float*)d_in[11];
    float* out = (float*)d_out;

    __half *corrh, *cor1h, *flo1h, *cath;
    __half *wc1h, *wc1l, *wc2h, *wc2l, *wf2h, *wf2l, *woh, *wol;
    cudaGetSymbolAddress((void**)&corrh, g_corr_h);
    cudaGetSymbolAddress((void**)&cor1h, g_cor1_h);
    cudaGetSymbolAddress((void**)&flo1h, g_flo1_h);
    cudaGetSymbolAddress((void**)&cath,  g_cat_h);
    cudaGetSymbolAddress((void**)&wc1h,  g_wc1_h);  cudaGetSymbolAddress((void**)&wc1l,  g_wc1_l);
    cudaGetSymbolAddress((void**)&wc2h,  g_wc2_h);  cudaGetSymbolAddress((void**)&wc2l,  g_wc2_l);
    cudaGetSymbolAddress((void**)&wf2h,  g_wf2_h);  cudaGetSymbolAddress((void**)&wf2l,  g_wf2_l);
    cudaGetSymbolAddress((void**)&woh,   g_wo_h);   cudaGetSymbolAddress((void**)&wol,   g_wo_l);

    cudaFuncSetAttribute(conv_mma_k, cudaFuncAttributeMaxDynamicSharedMemorySize, SMEM_BYTES);

    // prep
    wprep_k<<<128, 256>>>(wc1, 256, 324, 1, 256, 384, wc1h, wc1l);
    wprep_k<<<256, 256>>>(wc2, 192, 256, 9, 256, 256, wc2h, wc2l);
    wprep_k<<<128, 256>>>(wf2,  64, 128, 9, 128, 128, wf2h, wf2l);
    wprep_k<<<128, 256>>>(wo,  126, 256, 9, 128, 256, woh, wol);
    corr2nhwc_k<<<dim3(12, Hc, Bn), 256>>>(corr, corrh);

    // flo1 = relu(conv7x7(flow)) -> NHWC fp16 (Cpad 128)
    conv7x7_relu_k<<<dim3(Wc / 32, Hc / 8, Bn * 8), 256>>>(flow, wf1, bf1, flo1h);

    // cor1 = relu(conv1x1(corr))   [256ch, Cin 324->384]
    conv_mma_k<<<dim3(2, Hc, Bn), 256, SMEM_BYTES>>>(
        corrh, 384, 6, wc1h, wc1l, 256, bc1, 256, 1, 1, 0,
        cor1h, 256, 0, nullptr);
    // cat[:,0:192] = relu(conv3x3(cor1))
    conv_mma_k<<<dim3(2, Hc, Bn), 256, SMEM_BYTES>>>(
        cor1h, 256, 4, wc2h, wc2l, 256, bc2, 192, 9, 3, 1,
        cath, 256, 0, nullptr);
    // cat[:,192:256] = relu(conv3x3(flo1))
    conv_mma_k<<<dim3(1, Hc, Bn), 256, SMEM_BYTES>>>(
        flo1h, 128, 2, wf2h, wf2l, 128, bf2, 64, 9, 3, 1,
        cath, 256, 192, nullptr);
    // d_out[:,0:126] = relu(conv3x3(cat))  (fp32 NCHW)
    conv_mma_k<<<dim3(1, Hc, Bn), 256, SMEM_BYTES>>>(
        cath, 256, 4, woh, wol, 128, bo, 126, 9, 3, 1,
        nullptr, 128, 0, out);
    // d_out[:,126:128] = flow
    concat_flow_k<<<(Bn * 2 * HW + 255) / 256, 256>>>(flow, out);
}

// round 9
// speedup vs baseline: 6.8153x; 1.5176x over previous
#include <cuda_runtime.h>
#include <cuda_fp16.h>
#include <stdint.h>

#define Bn 8
#define Hc 96
#define Wc 128
#define HW (Hc*Wc)

// ---------------- scratch (__device__ globals; allocation-free rule) -------
__device__ __half g_corr_h[(size_t)Bn*HW*384];
__device__ __half g_cor1_h[(size_t)Bn*HW*256];
__device__ __half g_flo1_h[(size_t)Bn*HW*128];
__device__ __half g_cat_h [(size_t)Bn*HW*256];
__device__ __half g_wc1_h[1*256*384];
__device__ __half g_wc2_h[9*256*256];
__device__ __half g_wf2_h[9*128*128];
__device__ __half g_wo_h [9*128*256];

// ---------------- helpers ---------------------------------------------------
__device__ __forceinline__ uint32_t s2u(const void* p) {
    uint32_t a;
    asm("{ .reg .u64 t; cvta.to.shared.u64 t, %1; cvt.u32.u64 %0, t; }"
        : "=r"(a) : "l"(p));
    return a;
}
#define SWZ(x) ((x) ^ (((x) >> 3) & 0x70))

__device__ __forceinline__ void ldsm4(uint32_t* r, uint32_t addr) {
    asm volatile("ldmatrix.sync.aligned.m8n8.x4.shared.b16 {%0,%1,%2,%3}, [%4];"
        : "=r"(r[0]), "=r"(r[1]), "=r"(r[2]), "=r"(r[3]) : "r"(addr));
}
__device__ __forceinline__ void mma16816(float* d, const uint32_t* a,
                                          uint32_t b0, uint32_t b1) {
    asm volatile(
        "mma.sync.aligned.m16n8k16.row.col.f32.f16.f16.f32 "
        "{%0,%1,%2,%3}, {%4,%5,%6,%7}, {%8,%9}, {%0,%1,%2,%3};"
        : "+f"(d[0]), "+f"(d[1]), "+f"(d[2]), "+f"(d[3])
        : "r"(a[0]), "r"(a[1]), "r"(a[2]), "r"(a[3]), "r"(b0), "r"(b1));
}
__device__ __forceinline__ void cpa16(uint32_t s, const void* g, bool p) {
    asm volatile("cp.async.ca.shared.global [%0], [%1], 16, %2;"
        :: "r"(s), "l"(g), "r"(p ? 16u : 0u));
}
__device__ __forceinline__ void cpa_commit() {
    asm volatile("cp.async.commit_group;" ::: "memory");
}
__device__ __forceinline__ void cpa_wait0() {
    asm volatile("cp.async.wait_group 0;" ::: "memory");
}

// ---------------- weight prep (ALL layers, one launch): OIHW->tap-major fp16
__device__ __forceinline__ void prep1(const float* __restrict__ w, int cout,
                                      int cin, int taps, int coPad, int Cpad,
                                      __half* __restrict__ dst, size_t i)
{
    int ci = (int)(i % Cpad);
    size_t t = i / Cpad;
    int co = (int)(t % coPad);
    int tap = (int)(t / coPad);
    float v = 0.f;
    if (co < cout && ci < cin)
        v = w[((size_t)co * cin + ci) * taps + tap];
    dst[i] = __float2half(v);
}

__global__ void wprep_all_k(const float* __restrict__ wc1, const float* __restrict__ wc2,
                            const float* __restrict__ wf2, const float* __restrict__ wo,
                            __half* __restrict__ oc1, __half* __restrict__ oc2,
                            __half* __restrict__ of2, __half* __restrict__ oo)
{
    const size_t n1 = 98304, n2 = 589824, n3 = 147456, n4 = 294912;
    const size_t total = n1 + n2 + n3 + n4;
    for (size_t i = (size_t)blockIdx.x * blockDim.x + threadIdx.x; i < total;
         i += (size_t)gridDim.x * blockDim.x) {
        if (i < n1)                prep1(wc1, 256, 324, 1, 256, 384, oc1, i);
        else if (i < n1 + n2)      prep1(wc2, 192, 256, 9, 256, 256, oc2, i - n1);
        else if (i < n1 + n2 + n3) prep1(wf2,  64, 128, 9, 128, 128, of2, i - n1 - n2);
        else                       prep1(wo,  126, 256, 9, 128, 256, oo,  i - n1 - n2 - n3);
    }
}

// ---------------- corr NCHW fp32 -> NHWC fp16 (Cpad=384, zero pad) ----------
__global__ __launch_bounds__(256) void corr2nhwc_k(
    const float* __restrict__ corr, __half* __restrict__ oh)
{
    const int c0 = blockIdx.x * 32, h = blockIdx.y, b = blockIdx.z;
    __shared__ float t[32][129];
    for (int i = threadIdx.x; i < 32 * 128; i += 256) {
        int ci = i >> 7, px = i & 127;
        float v = 0.f;
        if (c0 + ci < 324)
            v = corr[((size_t)b * 324 + c0 + ci) * HW + h * Wc + px];
        t[ci][px] = v;
    }
    __syncthreads();
    for (int i = threadIdx.x; i < 32 * 128; i += 256) {
        int px = i >> 5, ci = i & 31;
        size_t o = (((size_t)b * Hc + h) * Wc + px) * 384 + c0 + ci;
        oh[o] = __float2half(t[ci][px]);
    }
}

// ---------------- conv7x7 (Cin=2, Cout=128) fp32 -> NHWC fp16 ---------------
__global__ __launch_bounds__(256) void conv7x7_relu_k(
    const float* __restrict__ in, const float* __restrict__ w,
    const float* __restrict__ bias, __half* __restrict__ oh)
{
    const int tid = threadIdx.x;
    const int tx = tid & 31, ty = tid >> 5;
    const int w0 = blockIdx.x * 32, h0 = blockIdx.y * 8;
    const int coTile = blockIdx.z & 7;
    const int b = blockIdx.z >> 3;
    const int coBase = coTile * 16;

    __shared__ float st[2][14][38];
    __shared__ float sw[16 * 2 * 49];

    const float* inb = in + (size_t)b * 2 * HW;
    for (int i = tid; i < 2 * 14 * 38; i += 256) {
        int ci = i / 532, r = (i % 532) / 38, c = i % 38;
        int hh = h0 + r - 3, ww = w0 + c - 3;
        float v = 0.f;
        if ((unsigned)hh < Hc && (unsigned)ww < Wc)
            v = inb[(size_t)ci * HW + hh * Wc + ww];
        st[ci][r][c] = v;
    }
    for (int i = tid; i < 1568; i += 256)
        sw[i] = w[(size_t)coBase * 98 + i];
    __syncthreads();

    float acc[16];
#pragma unroll
    for (int i = 0; i < 16; i++) acc[i] = 0.f;

#pragma unroll
    for (int ci = 0; ci < 2; ci++)
#pragma unroll
        for (int dy = 0; dy < 7; dy++) {
            float xv[7];
#pragma unroll
            for (int k = 0; k < 7; k++) xv[k] = st[ci][ty + dy][tx + k];
#pragma unroll
            for (int co = 0; co < 16; co++)
#pragma unroll
                for (int dx = 0; dx < 7; dx++)
                    acc[co] = fmaf(sw[co * 98 + ci * 49 + dy * 7 + dx], xv[dx], acc[co]);
        }

    const int hh = h0 + ty, ww = w0 + tx;
    __align__(16) __half vh[16];
#pragma unroll
    for (int co = 0; co < 16; co++)
        vh[co] = __float2half(fmaxf(acc[co] + bias[coBase + co], 0.f));
    size_t base = (((size_t)b * Hc + hh) * Wc + ww) * 128 + coBase;
    reinterpret_cast<uint4*>(oh + base)[0] = reinterpret_cast<uint4*>(vh)[0];
    reinterpret_cast<uint4*>(oh + base)[1] = reinterpret_cast<uint4*>(vh)[1];
}

// ---------------- HMMA conv-as-GEMM (single-pass fp16 weights) --------------
// Block: 256 thr / 8 warps; out tile 128co x 128px (one image row).
// A: 2-slot ring (16KB each), next step's weights staged during compute.
// B: 2-slot ring of [130px][64ci] tiles; dy-group G+1 prefetched at the first
//    step of group G. One commit + wait + sync per step.
// smem: A 32768 @0 ; B 2x16640 @32768; epilogue scratch reuses front region.
#define SMEM_BYTES 67584

__global__ __launch_bounds__(256, 2) void conv_mma_k(
    const __half* __restrict__ ah, int Cpad, int kcNum,
    const __half* __restrict__ wgh,
    int coPad, const float* __restrict__ bias, int coutUsed,
    int taps, int kw, int kr,
    __half* __restrict__ oh, int outCpad, int outCoff,
    float* __restrict__ of32)
{
    extern __shared__ __align__(16) char smem[];
    const uint32_t sA = s2u(smem);
    const uint32_t sB = sA + 32768u;

    const int tid = threadIdx.x;
    const int warp = tid >> 5, lane = tid & 31;
    const int mt = blockIdx.x, h = blockIdx.y, b = blockIdx.z;
    const int cbw = (warp >> 1) * 32;
    const int nbw = (warp & 1) * 64;
    const int gid = lane >> 2, tig = lane & 3;
    const int midx = lane >> 3, l7 = lane & 7;

    float d[16][4];
#pragma unroll
    for (int i = 0; i < 16; i++)
#pragma unroll
        for (int j = 0; j < 4; j++) d[i][j] = 0.f;

    const int nsteps = kcNum * taps;
    const int nG = kcNum * kw;          // dy-groups (square kernels)

    // stage A (fp16 weights) for step s into slot s&1
    auto stageA = [&](int s) {
        const int kcs = s / taps, tp = s % taps;
        const __half* wH = wgh + (size_t)kcs * 64;
        const uint32_t d0 = sA + (uint32_t)(s & 1) * 16384u;
#pragma unroll
        for (int j = 0; j < 4; j++) {
            int i = tid + j * 256;
            int row = i >> 3, c16 = i & 7;
            size_t o = ((size_t)tp * coPad + mt * 128 + row) * Cpad + c16 * 8;
            cpa16(d0 + SWZ((uint32_t)(row * 128 + c16 * 16)), wH + o, true);
        }
    };
    // stage B tile for dy-group G into slot G&1
    auto stageB = [&](int G) {
        const int kcs = G / kw, dyRow = G % kw;
        const int hh = h + dyRow - kr;
        const uint32_t dst = sB + (uint32_t)(G & 1) * 16640u;
        for (int i = tid; i < 1040; i += 256) {
            int row = i >> 3, c16 = i & 7;
            int px = row - 1;
            bool p = ((unsigned)px < Wc) && ((unsigned)hh < Hc);
            const __half* g = ah + (((size_t)b * Hc + hh) * Wc + px) * Cpad
                            + kcs * 64 + c16 * 8;
            cpa16(dst + SWZ(row * 128 + c16 * 16), p ? g : ah, p);
        }
    };

    // prologue
    stageB(0);
    stageA(0);
    cpa_commit();
    cpa_wait0();
    __syncthreads();

    for (int s = 0; s < nsteps; s++) {
        const int kc = s / taps, tap = s % taps;
        const int dyI = tap / kw, dx = tap % kw - kr;
        const int G = kc * kw + dyI;

        if (s + 1 < nsteps) stageA(s + 1);
        if (tap % kw == 0 && G + 1 < nG) stageB(G + 1);
        cpa_commit();

        const uint32_t A0 = sA + (uint32_t)(s & 1) * 16384u;
        const uint32_t Bt = sB + (uint32_t)(G & 1) * 16640u;
#pragma unroll
        for (int ks = 0; ks < 4; ks++) {
            uint32_t bf[4][4];
#pragma unroll
            for (int np = 0; np < 4; np++) {
                int brow = nbw + np * 16 + ((midx >> 1) << 3) + l7 + 1 + dx;
                uint32_t bd = Bt + SWZ((uint32_t)(brow * 128 + (2 * ks + (midx & 1)) * 16));
                ldsm4(bf[np], bd);
            }
            uint32_t a[2][4];
            ldsm4(a[0], A0 + SWZ((uint32_t)((cbw + ((midx & 1) << 3) + l7) * 128
                                            + (2 * ks + (midx >> 1)) * 16)));
            ldsm4(a[1], A0 + SWZ((uint32_t)((cbw + 16 + ((midx & 1) << 3) + l7) * 128
                                            + (2 * ks + (midx >> 1)) * 16)));
#pragma unroll
            for (int mi = 0; mi < 2; mi++)
#pragma unroll
                for (int ni = 0; ni < 8; ni++)
                    mma16816(d[mi * 8 + ni], a[mi],
                             bf[ni >> 1][(ni & 1) * 2], bf[ni >> 1][(ni & 1) * 2 + 1]);
        }
        cpa_wait0();
        __syncthreads();
    }

    // ---- epilogue: bias+relu, transpose through smem
    float bias4[4];
#pragma unroll
    for (int k2 = 0; k2 < 4; k2++) {
        int gco = mt * 128 + cbw + (k2 >> 1) * 16 + gid + (k2 & 1) * 8;
        bias4[k2] = (gco < coutUsed) ? bias[gco] : 0.f;
    }

    if (of32) {
        // [128co][128px + pad4] fp32 at smem+0 (67584 B)
#pragma unroll
        for (int mi = 0; mi < 2; mi++)
#pragma unroll
            for (int ni = 0; ni < 8; ni++)
#pragma unroll
                for (int k = 0; k < 4; k++) {
                    int co = cbw + mi * 16 + gid + ((k >> 1) << 3);
                    int px = nbw + ni * 8 + 2 * tig + (k & 1);
                    float v = fmaxf(d[mi * 8 + ni][k] + bias4[mi * 2 + (k >> 1)], 0.f);
                    *reinterpret_cast<float*>(smem + (co * 132 + px) * 4) = v;
                }
        __syncthreads();
        for (int i = tid; i < 128 * 32; i += 256) {
            int row = i >> 5, q = i & 31;
            int gco = mt * 128 + row;
            if (gco < coutUsed) {
                uint4 v = *reinterpret_cast<uint4*>(smem + (row * 132 + q * 4) * 4);
                *reinterpret_cast<uint4*>(
                    of32 + (((size_t)b * 128 + gco) * Hc + h) * Wc + q * 4) = v;
            }
        }
    } else {
        // [px 128][co 128 + pad8] fp16 at smem+0 (34816 B)
#pragma unroll
        for (int mi = 0; mi < 2; mi++)
#pragma unroll
            for (int ni = 0; ni < 8; ni++)
#pragma unroll
                for (int k = 0; k < 4; k++) {
                    int co = cbw + mi * 16 + gid + ((k >> 1) << 3);
                    int px = nbw + ni * 8 + 2 * tig + (k & 1);
                    float v = fmaxf(d[mi * 8 + ni][k] + bias4[mi * 2 + (k >> 1)], 0.f);
                    *reinterpret_cast<__half*>(smem + px * 272 + co * 2) = __float2half(v);
                }
        __syncthreads();
        for (int i = tid; i < 128 * 16; i += 256) {
            int row = i >> 4, q = i & 15;
            int gcoB = mt * 128 + q * 8;
            size_t dst = (((size_t)b * Hc + h) * Wc + row) * outCpad + outCoff + mt * 128 + q * 8;
            uint4 vh = *reinterpret_cast<uint4*>(smem + row * 272 + q * 16);
            if (gcoB + 8 <= coutUsed) {
                *reinterpret_cast<uint4*>(oh + dst) = vh;
            } else if (gcoB < coutUsed) {
                const __half* ph = reinterpret_cast<const __half*>(&vh);
                for (int e = 0; e < coutUsed - gcoB; e++) oh[dst + e] = ph[e];
            }
        }
    }
}

// append flow into output channels 126..127 (NCHW fp32)
__global__ void concat_flow_k(const float* __restrict__ flow, float* __restrict__ out)
{
    int i = blockIdx.x * 256 + threadIdx.x;
    if (i < Bn * 2 * HW) {
        int b = i / (2 * HW);
        int r = i % (2 * HW);
        out[(size_t)b * 128 * HW + (size_t)126 * HW + r] = flow[i];
    }
}

// ---------------------------------------------------------------------------
extern "C" void kernel_launch(void* const* d_in, const int* in_sizes, int n_in,
                              void* d_out, int out_size)
{
    const float* flow = (const float*)d_in[0];
    const float* corr = (const float*)d_in[1];
    const float* wc1  = (const float*)d_in[2];
    const float* bc1  = (const float*)d_in[3];
    const float* wc2  = (const float*)d_in[4];
    const float* bc2  = (const float*)d_in[5];
    const float* wf1  = (const float*)d_in[6];
    const float* bf1  = (const float*)d_in[7];
    const float* wf2  = (const float*)d_in[8];
    const float* bf2  = (const float*)d_in[9];
    const float* wo   = (const float*)d_in[10];
    const float* bo   = (const float*)d_in[11];
    float* out = (float*)d_out;

    __half *corrh, *cor1h, *flo1h, *cath, *wc1h, *wc2h, *wf2h, *woh;
    cudaGetSymbolAddress((void**)&corrh, g_corr_h);
    cudaGetSymbolAddress((void**)&cor1h, g_cor1_h);
    cudaGetSymbolAddress((void**)&flo1h, g_flo1_h);
    cudaGetSymbolAddress((void**)&cath,  g_cat_h);
    cudaGetSymbolAddress((void**)&wc1h,  g_wc1_h);
    cudaGetSymbolAddress((void**)&wc2h,  g_wc2_h);
    cudaGetSymbolAddress((void**)&wf2h,  g_wf2_h);
    cudaGetSymbolAddress((void**)&woh,   g_wo_h);

    cudaFuncSetAttribute(conv_mma_k, cudaFuncAttributeMaxDynamicSharedMemorySize, SMEM_BYTES);

    // launch 0: all weight prep (single kernel so ncu -s 5 hits the big conv)
    wprep_all_k<<<256, 256>>>(wc1, wc2, wf2, wo, wc1h, wc2h, wf2h, woh);
    // launch 1: corr layout
    corr2nhwc_k<<<dim3(12, Hc, Bn), 256>>>(corr, corrh);
    // launch 2: flo1 = relu(conv7x7(flow)) -> NHWC fp16 (Cpad 128)
    conv7x7_relu_k<<<dim3(Wc / 32, Hc / 8, Bn * 8), 256>>>(flow, wf1, bf1, flo1h);
    // launch 3: cor1 = relu(conv1x1(corr))
    conv_mma_k<<<dim3(2, Hc, Bn), 256, SMEM_BYTES>>>(
        corrh, 384, 6, wc1h, 256, bc1, 256, 1, 1, 0,
        cor1h, 256, 0, nullptr);
    // launch 4: cat[:,192:256] = relu(conv3x3(flo1))
    conv_mma_k<<<dim3(1, Hc, Bn), 256, SMEM_BYTES>>>(
        flo1h, 128, 2, wf2h, 128, bf2, 64, 9, 3, 1,
        cath, 256, 192, nullptr);
    // launch 5 (ncu target): cat[:,0:192] = relu(conv3x3(cor1))
    conv_mma_k<<<dim3(2, Hc, Bn), 256, SMEM_BYTES>>>(
        cor1h, 256, 4, wc2h, 256, bc2, 192, 9, 3, 1,
        cath, 256, 0, nullptr);
    // launch 6: d_out[:,0:126] = relu(conv3x3(cat))  (fp32 NCHW)
    conv_mma_k<<<dim3(1, Hc, Bn), 256, SMEM_BYTES>>>(
        cath, 256, 4, woh, 128, bo, 126, 9, 3, 1,
        nullptr, 128, 0, out);
    // launch 7: d_out[:,126:128] = flow
    concat_flow_k<<<(Bn * 2 * HW + 255) / 256, 256>>>(flow, out);
}

// round 10
// speedup vs baseline: 7.1531x; 1.0496x over previous
#include <cuda_runtime.h>
#include <cuda_fp16.h>
#include <stdint.h>

#define Bn 8
#define Hc 96
#define Wc 128
#define HW (Hc*Wc)

// ---------------- scratch (__device__ globals; allocation-free rule) -------
__device__ __half g_corr_h[(size_t)Bn*HW*384];
__device__ __half g_cor1_h[(size_t)Bn*HW*256];
__device__ __half g_flo1_h[(size_t)Bn*HW*128];
__device__ __half g_cat_h [(size_t)Bn*HW*256];
__device__ __half g_im7  [(size_t)Bn*HW*128];     // im2col of flow (7x7, Cin=2)
__device__ __half g_wc1_h[1*256*384];
__device__ __half g_wc2_h[9*256*256];
__device__ __half g_wf2_h[9*128*128];
__device__ __half g_wo_h [9*128*256];
__device__ __half g_wf1_h[128*128];               // im2col-matched 7x7 weights

// ---------------- helpers ---------------------------------------------------
__device__ __forceinline__ uint32_t s2u(const void* p) {
    uint32_t a;
    asm("{ .reg .u64 t; cvta.to.shared.u64 t, %1; cvt.u32.u64 %0, t; }"
        : "=r"(a) : "l"(p));
    return a;
}
#define SWZ(x) ((x) ^ (((x) >> 3) & 0x70))

__device__ __forceinline__ void ldsm4(uint32_t* r, uint32_t addr) {
    asm volatile("ldmatrix.sync.aligned.m8n8.x4.shared.b16 {%0,%1,%2,%3}, [%4];"
        : "=r"(r[0]), "=r"(r[1]), "=r"(r[2]), "=r"(r[3]) : "r"(addr));
}
__device__ __forceinline__ void mma16816(float* d, const uint32_t* a,
                                          uint32_t b0, uint32_t b1) {
    asm volatile(
        "mma.sync.aligned.m16n8k16.row.col.f32.f16.f16.f32 "
        "{%0,%1,%2,%3}, {%4,%5,%6,%7}, {%8,%9}, {%0,%1,%2,%3};"
        : "+f"(d[0]), "+f"(d[1]), "+f"(d[2]), "+f"(d[3])
        : "r"(a[0]), "r"(a[1]), "r"(a[2]), "r"(a[3]), "r"(b0), "r"(b1));
}
__device__ __forceinline__ void cpa16(uint32_t s, const void* g, bool p) {
    asm volatile("cp.async.ca.shared.global [%0], [%1], 16, %2;"
        :: "r"(s), "l"(g), "r"(p ? 16u : 0u));
}
__device__ __forceinline__ void cpa_commit() {
    asm volatile("cp.async.commit_group;" ::: "memory");
}
__device__ __forceinline__ void cpa_wait0() {
    asm volatile("cp.async.wait_group 0;" ::: "memory");
}

// ---------------- weight prep (ALL layers, one launch) ----------------------
__device__ __forceinline__ void prep1(const float* __restrict__ w, int cout,
                                      int cin, int taps, int coPad, int Cpad,
                                      __half* __restrict__ dst, size_t i)
{
    int ci = (int)(i % Cpad);
    size_t t = i / Cpad;
    int co = (int)(t % coPad);
    int tap = (int)(t / coPad);
    float v = 0.f;
    if (co < cout && ci < cin)
        v = w[((size_t)co * cin + ci) * taps + tap];
    dst[i] = __float2half(v);
}

__global__ void wprep_all_k(const float* __restrict__ wc1, const float* __restrict__ wc2,
                            const float* __restrict__ wf2, const float* __restrict__ wo,
                            const float* __restrict__ wf1,
                            __half* __restrict__ oc1, __half* __restrict__ oc2,
                            __half* __restrict__ of2, __half* __restrict__ oo,
                            __half* __restrict__ of1)
{
    const size_t n1 = 98304, n2 = 589824, n3 = 147456, n4 = 294912, n5 = 16384;
    const size_t total = n1 + n2 + n3 + n4 + n5;
    for (size_t i = (size_t)blockIdx.x * blockDim.x + threadIdx.x; i < total;
         i += (size_t)gridDim.x * blockDim.x) {
        if (i < n1)                     prep1(wc1, 256, 324, 1, 256, 384, oc1, i);
        else if (i < n1 + n2)           prep1(wc2, 192, 256, 9, 256, 256, oc2, i - n1);
        else if (i < n1 + n2 + n3)      prep1(wf2,  64, 128, 9, 128, 128, of2, i - n1 - n2);
        else if (i < n1 + n2 + n3 + n4) prep1(wo,  126, 256, 9, 128, 256, oo,  i - n1 - n2 - n3);
        else {
            size_t i5 = i - n1 - n2 - n3 - n4;
            int co = (int)(i5 >> 7), c = (int)(i5 & 127);
            float v = 0.f;
            if (c < 98)   // c = dyx*2 + ci ; w[co][ci][dyx]
                v = wf1[(size_t)co * 98 + (c & 1) * 49 + (c >> 1)];
            of1[i5] = __float2half(v);
        }
    }
}

// ---------------- corr NCHW fp32 -> NHWC fp16 (Cpad=384, zero pad) ----------
__global__ __launch_bounds__(256) void corr2nhwc_k(
    const float* __restrict__ corr, __half* __restrict__ oh)
{
    const int c0 = blockIdx.x * 32, h = blockIdx.y, b = blockIdx.z;
    __shared__ float t[32][129];
    for (int i = threadIdx.x; i < 32 * 128; i += 256) {
        int ci = i >> 7, px = i & 127;
        float v = 0.f;
        if (c0 + ci < 324)
            v = corr[((size_t)b * 324 + c0 + ci) * HW + h * Wc + px];
        t[ci][px] = v;
    }
    __syncthreads();
    for (int i = threadIdx.x; i < 32 * 128; i += 256) {
        int px = i >> 5, ci = i & 31;
        size_t o = (((size_t)b * Hc + h) * Wc + px) * 384 + c0 + ci;
        oh[o] = __float2half(t[ci][px]);
    }
}

// ---------------- im2col for the 7x7 conv: flow NCHW -> [B,H,W,128] fp16 ----
__global__ __launch_bounds__(128) void im2col7_k(
    const float* __restrict__ flow, __half* __restrict__ dst)
{
    const int w = threadIdx.x, h = blockIdx.x, b = blockIdx.y;
    __align__(16) __half v[128];
#pragma unroll
    for (int c = 98; c < 128; c++) v[c] = __float2half(0.f);
#pragma unroll
    for (int dy = 0; dy < 7; dy++) {
        int hh = h + dy - 3;
#pragma unroll
        for (int dx = 0; dx < 7; dx++) {
            int ww = w + dx - 3;
            bool p = ((unsigned)hh < Hc) && ((unsigned)ww < Wc);
#pragma unroll
            for (int ci = 0; ci < 2; ci++) {
                float f = p ? flow[((size_t)(b * 2 + ci) * Hc + hh) * Wc + ww] : 0.f;
                v[(dy * 7 + dx) * 2 + ci] = __float2half(f);
            }
        }
    }
    __half* o = dst + (((size_t)b * Hc + h) * Wc + w) * 128;
#pragma unroll
    for (int j = 0; j < 16; j++)
        reinterpret_cast<uint4*>(o)[j] = reinterpret_cast<uint4*>(v)[j];
}

// ---------------- HMMA conv-as-GEMM, 64x64 warp tiles ------------------------
// Block: 256 thr / 8 warps; tile 128co x 256px (TWO image rows h0, h0+1).
// Warp w: co half (w>>2)*64 ; quarter pq=w&3: row r=pq>>1, px base (pq&1)*64.
// Per warp-ks: 4 A ldsm + 4 B ldsm -> 32 mma (ratio 4.0).
// A: 2-slot ring (16KB), staged per step. B: kw+1 row-tiles [130px][64ci],
// staged once per kc (single buffer; exposed wait only kcNum times).
// smem: A 32768 @0 ; B (kw+1)*16640 @32768. Epilogue reuses whole region.
#define SMEM_BYTES 99328

__global__ __launch_bounds__(256, 1) void conv_mma2_k(
    const __half* __restrict__ ah, int Cpad, int kcNum,
    const __half* __restrict__ wgh,
    int coPad, const float* __restrict__ bias, int coutUsed,
    int taps, int kw, int kr,
    __half* __restrict__ oh, int outCpad, int outCoff,
    float* __restrict__ of32)
{
    extern __shared__ __align__(16) char smem[];
    const uint32_t sA = s2u(smem);
    const uint32_t sB = sA + 32768u;

    const int tid = threadIdx.x;
    const int warp = tid >> 5, lane = tid & 31;
    const int mt = blockIdx.x, h0 = blockIdx.y * 2, b = blockIdx.z;
    const int cw = (warp >> 2) * 64;
    const int pq = warp & 3;
    const int r = pq >> 1;
    const int pxb = (pq & 1) * 64;
    const int gid = lane >> 2, tig = lane & 3;
    const int midx = lane >> 3, l7 = lane & 7;

    float d[32][4];
#pragma unroll
    for (int i = 0; i < 32; i++)
#pragma unroll
        for (int j = 0; j < 4; j++) d[i][j] = 0.f;

    const int nsteps = kcNum * taps;
    const int nTile = kw + 1;

    auto stageA = [&](int s) {
        const int kcs = s / taps, tp = s % taps;
        const __half* src = wgh + (size_t)kcs * 64;
        const uint32_t d0 = sA + (uint32_t)(s & 1) * 16384u;
#pragma unroll
        for (int j = 0; j < 4; j++) {
            int i = tid + j * 256;
            int row = i >> 3, c16 = i & 7;
            cpa16(d0 + SWZ((uint32_t)(row * 128 + c16 * 16)),
                  src + ((size_t)tp * coPad + mt * 128 + row) * Cpad + c16 * 8, true);
        }
    };
    auto stageBall = [&](int kc) {
        const int tot = nTile * 1040;
        for (int i = tid; i < tot; i += 256) {
            int t = i / 1040, rem = i - t * 1040;
            int row = rem >> 3, c16 = rem & 7;
            int px = row - 1;
            int hh = h0 + t - kr;
            bool p = ((unsigned)px < Wc) && ((unsigned)hh < Hc);
            const __half* g = ah + (((size_t)b * Hc + hh) * Wc + px) * Cpad
                            + kc * 64 + c16 * 8;
            cpa16(sB + t * 16640 + SWZ(row * 128 + c16 * 16), p ? g : ah, p);
        }
    };

    for (int kc = 0; kc < kcNum; kc++) {
        __syncthreads();                 // prior B consumers done
        stageBall(kc);
        if (kc == 0) stageA(0);
        cpa_commit();
        cpa_wait0();
        __syncthreads();

        for (int tap = 0; tap < taps; tap++) {
            const int s = kc * taps + tap;
            if (s + 1 < nsteps) stageA(s + 1);
            cpa_commit();

            const int dy = tap / kw, dx = tap % kw - kr;
            const uint32_t Bt = sB + (uint32_t)((r + dy) * 16640);
            const uint32_t A0 = sA + (uint32_t)(s & 1) * 16384u;
#pragma unroll
            for (int ks = 0; ks < 4; ks++) {
                uint32_t bf[4][4];
#pragma unroll
                for (int np = 0; np < 4; np++) {
                    int brow = pxb + np * 16 + ((midx >> 1) << 3) + l7 + 1 + dx;
                    ldsm4(bf[np], Bt + SWZ((uint32_t)(brow * 128 + (2 * ks + (midx & 1)) * 16)));
                }
                uint32_t a[4][4];
#pragma unroll
                for (int mi = 0; mi < 4; mi++)
                    ldsm4(a[mi], A0 + SWZ((uint32_t)((cw + mi * 16 + ((midx & 1) << 3) + l7) * 128
                                                     + (2 * ks + (midx >> 1)) * 16)));
#pragma unroll
                for (int mi = 0; mi < 4; mi++)
#pragma unroll
                    for (int ni = 0; ni < 8; ni++)
                        mma16816(d[mi * 8 + ni], a[mi],
                                 bf[ni >> 1][(ni & 1) * 2], bf[ni >> 1][(ni & 1) * 2 + 1]);
            }
            cpa_wait0();
            __syncthreads();
        }
    }

    // ---- epilogue
    float bias8[4][2];
#pragma unroll
    for (int mi = 0; mi < 4; mi++)
#pragma unroll
        for (int kk = 0; kk < 2; kk++) {
            int gco = mt * 128 + cw + mi * 16 + gid + kk * 8;
            bias8[mi][kk] = (gco < coutUsed) ? bias[gco] : 0.f;
        }

    if (of32) {
        // two passes over co halves: [64co][256px + pad4] fp32 (66560 B)
        for (int p = 0; p < 2; p++) {
            if ((cw >> 6) == p) {
#pragma unroll
                for (int mi = 0; mi < 4; mi++)
#pragma unroll
                    for (int ni = 0; ni < 8; ni++)
#pragma unroll
                        for (int k = 0; k < 4; k++) {
                            int co = (cw & 63) + mi * 16 + gid + ((k >> 1) << 3);
                            int px = r * 128 + pxb + ni * 8 + 2 * tig + (k & 1);
                            float v = fmaxf(d[mi * 8 + ni][k] + bias8[mi][k >> 1], 0.f);
                            *reinterpret_cast<float*>(smem + (co * 260 + px) * 4) = v;
                        }
            }
            __syncthreads();
            for (int i = tid; i < 64 * 64; i += 256) {
                int row = i >> 6, q = i & 63;
                int gco = mt * 128 + p * 64 + row;
                if (gco < coutUsed) {
                    int px0 = q * 4;
                    int hh = h0 + (px0 >> 7), pxr = px0 & 127;
                    uint4 v = *reinterpret_cast<uint4*>(smem + (row * 260 + px0) * 4);
                    *reinterpret_cast<uint4*>(
                        of32 + (((size_t)b * 128 + gco) * Hc + hh) * Wc + pxr) = v;
                }
            }
            __syncthreads();
        }
    } else {
        // [px 256][co 128 + pad8] fp16 (69632 B)
#pragma unroll
        for (int mi = 0; mi < 4; mi++)
#pragma unroll
            for (int ni = 0; ni < 8; ni++)
#pragma unroll
                for (int k = 0; k < 4; k++) {
                    int co = cw + mi * 16 + gid + ((k >> 1) << 3);
                    int px = r * 128 + pxb + ni * 8 + 2 * tig + (k & 1);
                    float v = fmaxf(d[mi * 8 + ni][k] + bias8[mi][k >> 1], 0.f);
                    *reinterpret_cast<__half*>(smem + px * 272 + co * 2) = __float2half(v);
                }
        __syncthreads();
        for (int i = tid; i < 256 * 16; i += 256) {
            int row = i >> 4, q = i & 15;           // row = px (0..255)
            int hh = h0 + (row >> 7), pxr = row & 127;
            int gcoB = mt * 128 + q * 8;
            size_t dst = (((size_t)b * Hc + hh) * Wc + pxr) * outCpad + outCoff + mt * 128 + q * 8;
            uint4 vh = *reinterpret_cast<uint4*>(smem + row * 272 + q * 16);
            if (gcoB + 8 <= coutUsed) {
                *reinterpret_cast<uint4*>(oh + dst) = vh;
            } else if (gcoB < coutUsed) {
                const __half* ph = reinterpret_cast<const __half*>(&vh);
                for (int e = 0; e < coutUsed - gcoB; e++) oh[dst + e] = ph[e];
            }
        }
    }
}

// append flow into output channels 126..127 (NCHW fp32)
__global__ void concat_flow_k(const float* __restrict__ flow, float* __restrict__ out)
{
    int i = blockIdx.x * 256 + threadIdx.x;
    if (i < Bn * 2 * HW) {
        int b = i / (2 * HW);
        int r = i % (2 * HW);
        out[(size_t)b * 128 * HW + (size_t)126 * HW + r] = flow[i];
    }
}

// ---------------------------------------------------------------------------
extern "C" void kernel_launch(void* const* d_in, const int* in_sizes, int n_in,
                              void* d_out, int out_size)
{
    const float* flow = (const float*)d_in[0];
    const float* corr = (const float*)d_in[1];
    const float* wc1  = (const float*)d_in[2];
    const float* bc1  = (const float*)d_in[3];
    const float* wc2  = (const float*)d_in[4];
    const float* bc2  = (const float*)d_in[5];
    const float* wf1  = (const float*)d_in[6];
    const float* bf1  = (const float*)d_in[7];
    const float* wf2  = (const float*)d_in[8];
    const float* bf2  = (const float*)d_in[9];
    const float* wo   = (const float*)d_in[10];
    const float* bo   = (const float*)d_in[11];
    float* out = (float*)d_out;

    __half *corrh, *cor1h, *flo1h, *cath, *im7, *wc1h, *wc2h, *wf2h, *woh, *wf1h;
    cudaGetSymbolAddress((void**)&corrh, g_corr_h);
    cudaGetSymbolAddress((void**)&cor1h, g_cor1_h);
    cudaGetSymbolAddress((void**)&flo1h, g_flo1_h);
    cudaGetSymbolAddress((void**)&cath,  g_cat_h);
    cudaGetSymbolAddress((void**)&im7,   g_im7);
    cudaGetSymbolAddress((void**)&wc1h,  g_wc1_h);
    cudaGetSymbolAddress((void**)&wc2h,  g_wc2_h);
    cudaGetSymbolAddress((void**)&wf2h,  g_wf2_h);
    cudaGetSymbolAddress((void**)&woh,   g_wo_h);
    cudaGetSymbolAddress((void**)&wf1h,  g_wf1_h);

    cudaFuncSetAttribute(conv_mma2_k, cudaFuncAttributeMaxDynamicSharedMemorySize, SMEM_BYTES);

    // 0: all weight prep
    wprep_all_k<<<256, 256>>>(wc1, wc2, wf2, wo, wf1, wc1h, wc2h, wf2h, woh, wf1h);
    // 1: corr layout
    corr2nhwc_k<<<dim3(12, Hc, Bn), 256>>>(corr, corrh);
    // 2: im2col of flow for the 7x7 conv
    im2col7_k<<<dim3(Hc, Bn), 128>>>(flow, im7);
    // 3: flo1 = relu(conv7x7(flow)) == im7 GEMM (Cpad=128, kc=2, 1x1 form)
    conv_mma2_k<<<dim3(1, Hc / 2, Bn), 256, SMEM_BYTES>>>(
        im7, 128, 2, wf1h, 128, bf1, 128, 1, 1, 0,
        flo1h, 128, 0, nullptr);
    // 4: cor1 = relu(conv1x1(corr))
    conv_mma2_k<<<dim3(2, Hc / 2, Bn), 256, SMEM_BYTES>>>(
        corrh, 384, 6, wc1h, 256, bc1, 256, 1, 1, 0,
        cor1h, 256, 0, nullptr);
    // 5 (ncu target): cat[:,0:192] = relu(conv3x3(cor1))
    conv_mma2_k<<<dim3(2, Hc / 2, Bn), 256, SMEM_BYTES>>>(
        cor1h, 256, 4, wc2h, 256, bc2, 192, 9, 3, 1,
        cath, 256, 0, nullptr);
    // 6: cat[:,192:256] = relu(conv3x3(flo1))
    conv_mma2_k<<<dim3(1, Hc / 2, Bn), 256, SMEM_BYTES>>>(
        flo1h, 128, 2, wf2h, 128, bf2, 64, 9, 3, 1,
        cath, 256, 192, nullptr);
    // 7: d_out[:,0:126] = relu(conv3x3(cat))  (fp32 NCHW)
    conv_mma2_k<<<dim3(1, Hc / 2, Bn), 256, SMEM_BYTES>>>(
        cath, 256, 4, woh, 128, bo, 126, 9, 3, 1,
        nullptr, 128, 0, out);
    // 8: d_out[:,126:128] = flow
    concat_flow_k<<<(Bn * 2 * HW + 255) / 256, 256>>>(flow, out);
}

// round 11
// speedup vs baseline: 8.2964x; 1.1598x over previous
#include <cuda_runtime.h>
#include <cuda_fp16.h>
#include <stdint.h>

#define Bn 8
#define Hc 96
#define Wc 128
#define HW (Hc*Wc)

// ---------------- scratch (__device__ globals; allocation-free rule) -------
__device__ __half g_corr_h[(size_t)Bn*HW*384];
__device__ __half g_cor1_h[(size_t)Bn*HW*256];
__device__ __half g_flo1_h[(size_t)Bn*HW*128];
__device__ __half g_cat_h [(size_t)Bn*HW*256];
__device__ __half g_im7  [(size_t)Bn*HW*128];     // im2col of flow (7x7, Cin=2)
__device__ __half g_wc1_h[1*256*384];
__device__ __half g_wc2_h[9*256*256];
__device__ __half g_wf2_h[9*128*128];
__device__ __half g_wo_h [9*128*256];
__device__ __half g_wf1_h[128*128];               // im2col-matched 7x7 weights

// ---------------- helpers ---------------------------------------------------
__device__ __forceinline__ uint32_t s2u(const void* p) {
    uint32_t a;
    asm("{ .reg .u64 t; cvta.to.shared.u64 t, %1; cvt.u32.u64 %0, t; }"
        : "=r"(a) : "l"(p));
    return a;
}
#define SWZ(x) ((x) ^ (((x) >> 3) & 0x70))

__device__ __forceinline__ void ldsm4(uint32_t* r, uint32_t addr) {
    asm volatile("ldmatrix.sync.aligned.m8n8.x4.shared.b16 {%0,%1,%2,%3}, [%4];"
        : "=r"(r[0]), "=r"(r[1]), "=r"(r[2]), "=r"(r[3]) : "r"(addr));
}
__device__ __forceinline__ void mma16816(float* d, const uint32_t* a,
                                          uint32_t b0, uint32_t b1) {
    asm volatile(
        "mma.sync.aligned.m16n8k16.row.col.f32.f16.f16.f32 "
        "{%0,%1,%2,%3}, {%4,%5,%6,%7}, {%8,%9}, {%0,%1,%2,%3};"
        : "+f"(d[0]), "+f"(d[1]), "+f"(d[2]), "+f"(d[3])
        : "r"(a[0]), "r"(a[1]), "r"(a[2]), "r"(a[3]), "r"(b0), "r"(b1));
}
__device__ __forceinline__ void cpa16(uint32_t s, const void* g, bool p) {
    asm volatile("cp.async.ca.shared.global [%0], [%1], 16, %2;"
        :: "r"(s), "l"(g), "r"(p ? 16u : 0u));
}
__device__ __forceinline__ void cpa_commit() {
    asm volatile("cp.async.commit_group;" ::: "memory");
}
__device__ __forceinline__ void cpa_wait0() {
    asm volatile("cp.async.wait_group 0;" ::: "memory");
}

// ---------------- weight prep (ALL layers, one launch) ----------------------
__device__ __forceinline__ void prep1(const float* __restrict__ w, int cout,
                                      int cin, int taps, int coPad, int Cpad,
                                      __half* __restrict__ dst, size_t i)
{
    int ci = (int)(i % Cpad);
    size_t t = i / Cpad;
    int co = (int)(t % coPad);
    int tap = (int)(t / coPad);
    float v = 0.f;
    if (co < cout && ci < cin)
        v = w[((size_t)co * cin + ci) * taps + tap];
    dst[i] = __float2half(v);
}

__global__ void wprep_all_k(const float* __restrict__ wc1, const float* __restrict__ wc2,
                            const float* __restrict__ wf2, const float* __restrict__ wo,
                            const float* __restrict__ wf1,
                            __half* __restrict__ oc1, __half* __restrict__ oc2,
                            __half* __restrict__ of2, __half* __restrict__ oo,
                            __half* __restrict__ of1)
{
    const size_t n1 = 98304, n2 = 589824, n3 = 147456, n4 = 294912, n5 = 16384;
    const size_t total = n1 + n2 + n3 + n4 + n5;
    for (size_t i = (size_t)blockIdx.x * blockDim.x + threadIdx.x; i < total;
         i += (size_t)gridDim.x * blockDim.x) {
        if (i < n1)                     prep1(wc1, 256, 324, 1, 256, 384, oc1, i);
        else if (i < n1 + n2)           prep1(wc2, 192, 256, 9, 256, 256, oc2, i - n1);
        else if (i < n1 + n2 + n3)      prep1(wf2,  64, 128, 9, 128, 128, of2, i - n1 - n2);
        else if (i < n1 + n2 + n3 + n4) prep1(wo,  126, 256, 9, 128, 256, oo,  i - n1 - n2 - n3);
        else {
            size_t i5 = i - n1 - n2 - n3 - n4;
            int co = (int)(i5 >> 7), c = (int)(i5 & 127);
            float v = 0.f;
            if (c < 98)   // c = dyx*2 + ci ; w[co][ci][dyx]
                v = wf1[(size_t)co * 98 + (c & 1) * 49 + (c >> 1)];
            of1[i5] = __float2half(v);
        }
    }
}

// ---------------- corr NCHW fp32 -> NHWC fp16 (Cpad=384, zero pad) ----------
__global__ __launch_bounds__(256) void corr2nhwc_k(
    const float* __restrict__ corr, __half* __restrict__ oh)
{
    const int c0 = blockIdx.x * 32, h = blockIdx.y, b = blockIdx.z;
    __shared__ float t[32][129];
    for (int i = threadIdx.x; i < 32 * 128; i += 256) {
        int ci = i >> 7, px = i & 127;
        float v = 0.f;
        if (c0 + ci < 324)
            v = corr[((size_t)b * 324 + c0 + ci) * HW + h * Wc + px];
        t[ci][px] = v;
    }
    __syncthreads();
    for (int i = threadIdx.x; i < 32 * 128; i += 256) {
        int px = i >> 5, ci = i & 31;
        size_t o = (((size_t)b * Hc + h) * Wc + px) * 384 + c0 + ci;
        oh[o] = __float2half(t[ci][px]);
    }
}

// ---------------- im2col for the 7x7 conv: flow NCHW -> [B,H,W,128] fp16 ----
__global__ __launch_bounds__(128) void im2col7_k(
    const float* __restrict__ flow, __half* __restrict__ dst)
{
    const int w = threadIdx.x, h = blockIdx.x, b = blockIdx.y;
    __align__(16) __half v[128];
#pragma unroll
    for (int c = 98; c < 128; c++) v[c] = __float2half(0.f);
#pragma unroll
    for (int dy = 0; dy < 7; dy++) {
        int hh = h + dy - 3;
#pragma unroll
        for (int dx = 0; dx < 7; dx++) {
            int ww = w + dx - 3;
            bool p = ((unsigned)hh < Hc) && ((unsigned)ww < Wc);
#pragma unroll
            for (int ci = 0; ci < 2; ci++) {
                float f = p ? flow[((size_t)(b * 2 + ci) * Hc + hh) * Wc + ww] : 0.f;
                v[(dy * 7 + dx) * 2 + ci] = __float2half(f);
            }
        }
    }
    __half* o = dst + (((size_t)b * Hc + h) * Wc + w) * 128;
#pragma unroll
    for (int j = 0; j < 16; j++)
        reinterpret_cast<uint4*>(o)[j] = reinterpret_cast<uint4*>(v)[j];
}

// ---------------- HMMA conv-as-GEMM, 64co x 512px blocks ---------------------
// Block: 256 thr / 8 warps; tile 64co x 512px (FOUR image rows h0..h0+3).
// Warp w: row r4=w>>1 (0..3), px half pxb=(w&1)*64; all warps share A (64 co).
// Per warp-ks: 4 A ldsm + 4 B ldsm -> 32 mma (ratio 4.0).
// A: 2-slot ring (8KB each), staged per step (fully overlapped).
// B: (4 + kw - 1) row-tiles [130px][64ci], staged once per kc.
// smem: A 16384 @0 ; B <=6*16640 @16384 (total 116224). Epilogue reuses all.
#define SMEM_BYTES 116224

__global__ __launch_bounds__(256, 1) void conv_mma3_k(
    const __half* __restrict__ ah, int Cpad, int kcNum,
    const __half* __restrict__ wgh,
    int coPad, const float* __restrict__ bias, int coutUsed,
    int taps, int kw, int kr,
    __half* __restrict__ oh, int outCpad, int outCoff,
    float* __restrict__ of32)
{
    extern __shared__ __align__(16) char smem[];
    const uint32_t sA = s2u(smem);
    const uint32_t sB = sA + 16384u;

    const int tid = threadIdx.x;
    const int warp = tid >> 5, lane = tid & 31;
    const int mt = blockIdx.x, h0 = blockIdx.y * 4, b = blockIdx.z;
    const int r4 = warp >> 1;             // image row within block (0..3)
    const int pxb = (warp & 1) * 64;      // px half
    const int gid = lane >> 2, tig = lane & 3;
    const int midx = lane >> 3, l7 = lane & 7;

    float d[32][4];
#pragma unroll
    for (int i = 0; i < 32; i++)
#pragma unroll
        for (int j = 0; j < 4; j++) d[i][j] = 0.f;

    const int nsteps = kcNum * taps;
    const int nTile = 4 + kw - 1;

    // stage A (64 co x 64 ci fp16) for step s into slot s&1
    auto stageA = [&](int s) {
        const int kcs = s / taps, tp = s % taps;
        const __half* src = wgh + (size_t)kcs * 64;
        const uint32_t d0 = sA + (uint32_t)(s & 1) * 8192u;
#pragma unroll
        for (int j = 0; j < 2; j++) {
            int i = tid + j * 256;
            int row = i >> 3, c16 = i & 7;
            cpa16(d0 + SWZ((uint32_t)(row * 128 + c16 * 16)),
                  src + ((size_t)tp * coPad + mt * 64 + row) * Cpad + c16 * 8, true);
        }
    };
    // stage all B row-tiles for chunk kc
    auto stageBall = [&](int kc) {
        const int tot = nTile * 1040;
        for (int i = tid; i < tot; i += 256) {
            int t = i / 1040, rem = i - t * 1040;
            int row = rem >> 3, c16 = rem & 7;
            int px = row - 1;
            int hh = h0 + t - kr;
            bool p = ((unsigned)px < Wc) && ((unsigned)hh < Hc);
            const __half* g = ah + (((size_t)b * Hc + hh) * Wc + px) * Cpad
                            + kc * 64 + c16 * 8;
            cpa16(sB + t * 16640 + SWZ(row * 128 + c16 * 16), p ? g : ah, p);
        }
    };

    for (int kc = 0; kc < kcNum; kc++) {
        __syncthreads();                 // prior B consumers done
        stageBall(kc);
        if (kc == 0) stageA(0);
        cpa_commit();
        cpa_wait0();
        __syncthreads();

        for (int tap = 0; tap < taps; tap++) {
            const int s = kc * taps + tap;
            if (s + 1 < nsteps) stageA(s + 1);
            cpa_commit();

            const int dy = tap / kw, dx = tap % kw - kr;
            const uint32_t Bt = sB + (uint32_t)((r4 + dy) * 16640);
            const uint32_t A0 = sA + (uint32_t)(s & 1) * 8192u;
#pragma unroll
            for (int ks = 0; ks < 4; ks++) {
                uint32_t bf[4][4];
#pragma unroll
                for (int np = 0; np < 4; np++) {
                    int brow = pxb + np * 16 + ((midx >> 1) << 3) + l7 + 1 + dx;
                    ldsm4(bf[np], Bt + SWZ((uint32_t)(brow * 128 + (2 * ks + (midx & 1)) * 16)));
                }
                uint32_t a[4][4];
#pragma unroll
                for (int mi = 0; mi < 4; mi++)
                    ldsm4(a[mi], A0 + SWZ((uint32_t)((mi * 16 + ((midx & 1) << 3) + l7) * 128
                                                     + (2 * ks + (midx >> 1)) * 16)));
#pragma unroll
                for (int mi = 0; mi < 4; mi++)
#pragma unroll
                    for (int ni = 0; ni < 8; ni++)
                        mma16816(d[mi * 8 + ni], a[mi],
                                 bf[ni >> 1][(ni & 1) * 2], bf[ni >> 1][(ni & 1) * 2 + 1]);
            }
            cpa_wait0();
            __syncthreads();
        }
    }

    // ---- epilogue
    float bias8[4][2];
#pragma unroll
    for (int mi = 0; mi < 4; mi++)
#pragma unroll
        for (int kk = 0; kk < 2; kk++) {
            int gco = mt * 64 + mi * 16 + gid + kk * 8;
            bias8[mi][kk] = (gco < coutUsed) ? bias[gco] : 0.f;
        }

    if (of32) {
        // two passes over 32-co halves: [32co][512px + pad4] fp32 (66048 B)
        for (int p = 0; p < 2; p++) {
#pragma unroll
            for (int mi = 0; mi < 4; mi++) {
                if ((mi >> 1) != p) continue;
#pragma unroll
                for (int ni = 0; ni < 8; ni++)
#pragma unroll
                    for (int k = 0; k < 4; k++) {
                        int coL = (mi & 1) * 16 + gid + ((k >> 1) << 3);
                        int px = r4 * 128 + pxb + ni * 8 + 2 * tig + (k & 1);
                        float v = fmaxf(d[mi * 8 + ni][k] + bias8[mi][k >> 1], 0.f);
                        *reinterpret_cast<float*>(smem + (coL * 516 + px) * 4) = v;
                    }
            }
            __syncthreads();
            for (int i = tid; i < 32 * 128; i += 256) {
                int row = i >> 7, q = i & 127;
                int gco = mt * 64 + p * 32 + row;
                if (gco < coutUsed) {
                    int px0 = q * 4;
                    int hh = h0 + (px0 >> 7), pxr = px0 & 127;
                    uint4 v = *reinterpret_cast<uint4*>(smem + (row * 516 + px0) * 4);
                    *reinterpret_cast<uint4*>(
                        of32 + (((size_t)b * 128 + gco) * Hc + hh) * Wc + pxr) = v;
                }
            }
            __syncthreads();
        }
    } else {
        // [px 512][co 64 + pad8] fp16 (73728 B)
#pragma unroll
        for (int mi = 0; mi < 4; mi++)
#pragma unroll
            for (int ni = 0; ni < 8; ni++)
#pragma unroll
                for (int k = 0; k < 4; k++) {
                    int co = mi * 16 + gid + ((k >> 1) << 3);
                    int px = r4 * 128 + pxb + ni * 8 + 2 * tig + (k & 1);
                    float v = fmaxf(d[mi * 8 + ni][k] + bias8[mi][k >> 1], 0.f);
                    *reinterpret_cast<__half*>(smem + px * 144 + co * 2) = __float2half(v);
                }
        __syncthreads();
        for (int i = tid; i < 512 * 8; i += 256) {
            int row = i >> 3, q = i & 7;            // row = px (0..511)
            int hh = h0 + (row >> 7), pxr = row & 127;
            int gcoB = mt * 64 + q * 8;
            size_t dst = (((size_t)b * Hc + hh) * Wc + pxr) * outCpad + outCoff + mt * 64 + q * 8;
            uint4 vh = *reinterpret_cast<uint4*>(smem + row * 144 + q * 16);
            if (gcoB + 8 <= coutUsed) {
                *reinterpret_cast<uint4*>(oh + dst) = vh;
            } else if (gcoB < coutUsed) {
                const __half* ph = reinterpret_cast<const __half*>(&vh);
                for (int e = 0; e < coutUsed - gcoB; e++) oh[dst + e] = ph[e];
            }
        }
    }
}

// append flow into output channels 126..127 (NCHW fp32)
__global__ void concat_flow_k(const float* __restrict__ flow, float* __restrict__ out)
{
    int i = blockIdx.x * 256 + threadIdx.x;
    if (i < Bn * 2 * HW) {
        int b = i / (2 * HW);
        int r = i % (2 * HW);
        out[(size_t)b * 128 * HW + (size_t)126 * HW + r] = flow[i];
    }
}

// ---------------------------------------------------------------------------
extern "C" void kernel_launch(void* const* d_in, const int* in_sizes, int n_in,
                              void* d_out, int out_size)
{
    const float* flow = (const float*)d_in[0];
    const float* corr = (const float*)d_in[1];
    const float* wc1  = (const float*)d_in[2];
    const float* bc1  = (const float*)d_in[3];
    const float* wc2  = (const float*)d_in[4];
    const float* bc2  = (const float*)d_in[5];
    const float* wf1  = (const float*)d_in[6];
    const float* bf1  = (const float*)d_in[7];
    const float* wf2  = (const float*)d_in[8];
    const float* bf2  = (const float*)d_in[9];
    const float* wo   = (const float*)d_in[10];
    const float* bo   = (const float*)d_in[11];
    float* out = (float*)d_out;

    __half *corrh, *cor1h, *flo1h, *cath, *im7, *wc1h, *wc2h, *wf2h, *woh, *wf1h;
    cudaGetSymbolAddress((void**)&corrh, g_corr_h);
    cudaGetSymbolAddress((void**)&cor1h, g_cor1_h);
    cudaGetSymbolAddress((void**)&flo1h, g_flo1_h);
    cudaGetSymbolAddress((void**)&cath,  g_cat_h);
    cudaGetSymbolAddress((void**)&im7,   g_im7);
    cudaGetSymbolAddress((void**)&wc1h,  g_wc1_h);
    cudaGetSymbolAddress((void**)&wc2h,  g_wc2_h);
    cudaGetSymbolAddress((void**)&wf2h,  g_wf2_h);
    cudaGetSymbolAddress((void**)&woh,   g_wo_h);
    cudaGetSymbolAddress((void**)&wf1h,  g_wf1_h);

    cudaFuncSetAttribute(conv_mma3_k, cudaFuncAttributeMaxDynamicSharedMemorySize, SMEM_BYTES);

    // 0: all weight prep
    wprep_all_k<<<256, 256>>>(wc1, wc2, wf2, wo, wf1, wc1h, wc2h, wf2h, woh, wf1h);
    // 1: im2col of flow for the 7x7 conv
    im2col7_k<<<dim3(Hc, Bn), 128>>>(flow, im7);
    // 2: corr layout
    corr2nhwc_k<<<dim3(12, Hc, Bn), 256>>>(corr, corrh);
    // 3: cor1 = relu(conv1x1(corr))            M=256 -> x=4
    conv_mma3_k<<<dim3(4, Hc / 4, Bn), 256, SMEM_BYTES>>>(
        corrh, 384, 6, wc1h, 256, bc1, 256, 1, 1, 0,
        cor1h, 256, 0, nullptr);
    // 4: flo1 = relu(conv7x7(flow)) == im7 GEMM  M=128 -> x=2
    conv_mma3_k<<<dim3(2, Hc / 4, Bn), 256, SMEM_BYTES>>>(
        im7, 128, 2, wf1h, 128, bf1, 128, 1, 1, 0,
        flo1h, 128, 0, nullptr);
    // 5 (ncu target): cat[:,0:192] = relu(conv3x3(cor1))  M=192 -> x=3
    conv_mma3_k<<<dim3(3, Hc / 4, Bn), 256, SMEM_BYTES>>>(
        cor1h, 256, 4, wc2h, 256, bc2, 192, 9, 3, 1,
        cath, 256, 0, nullptr);
    // 6: cat[:,192:256] = relu(conv3x3(flo1))  M=64 -> x=1
    conv_mma3_k<<<dim3(1, Hc / 4, Bn), 256, SMEM_BYTES>>>(
        flo1h, 128, 2, wf2h, 128, bf2, 64, 9, 3, 1,
        cath, 256, 192, nullptr);
    // 7: d_out[:,0:126] = relu(conv3x3(cat))   (fp32 NCHW) M=128 -> x=2
    conv_mma3_k<<<dim3(2, Hc / 4, Bn), 256, SMEM_BYTES>>>(
        cath, 256, 4, woh, 128, bo, 126, 9, 3, 1,
        nullptr, 128, 0, out);
    // 8: d_out[:,126:128] = flow
    concat_flow_k<<<(Bn * 2 * HW + 255) / 256, 256>>>(flow, out);
}